// round 10
// baseline (speedup 1.0000x reference)
#include <cuda_runtime.h>
#include <cuda_fp16.h>
#include <cstdint>

#define B_ 4
#define S_ 1024
#define D_ 768
#define H_ 12
#define L_ 4
#define V_ 8000
#define VP 8064
#define FF_ 3072
#define TOK 4096
#define QKV 2304
#define EPSF 1e-5f
typedef __half h16;
typedef __half2 h162;

// ---------------- scratch ----------------
__device__ float g_x[TOK * D_];
__device__ h16 g_xn[TOK * D_];
__device__ h16 g_qkv[TOK * QKV];
__device__ h16 g_cq[TOK * D_];
__device__ h16 g_o[TOK * D_];
__device__ h16 g_mem[TOK * D_];
__device__ h16 g_ffh[TOK * FF_];
__device__ h16 g_ap[(long)B_ * H_ * S_ * S_];
__device__ h16 g_vt[(long)B_ * D_ * S_];
__device__ h16 g_wea[L_*4*D_*D_];
__device__ h16 g_wda[L_*8*D_*D_];
__device__ h16 g_we1[L_*FF_*D_];
__device__ h16 g_we2[L_*D_*FF_];
__device__ h16 g_wd1[L_*FF_*D_];
__device__ h16 g_wd2[L_*D_*FF_];
__device__ h16 g_wo[(long)VP * D_];

// ---------------- transpose+convert: slice z of W[K,N] fp32 -> [Npad,K] fp16 ----------------
// 64k x 32n tiles, vectorized h162 writes. Requires K % 64 == 0 (true for 768/3072).
__global__ void ttrans_kernel(const float* __restrict__ W, h16* __restrict__ Wh,
                              int K, int N, int Npad)
{
    __shared__ float t[64][33];
    int z = blockIdx.z;
    W += (long)z * K * N; Wh += (long)z * Npad * K;
    int n0 = blockIdx.x * 32, k0 = blockIdx.y * 64;
    int tx = threadIdx.x, ty = threadIdx.y;   // 32 x 8
#pragma unroll
    for (int j = 0; j < 8; j++) {
        int k = k0 + ty + 8 * j, n = n0 + tx;
        t[ty + 8 * j][tx] = (n < N) ? W[(long)k * N + n] : 0.f;
    }
    __syncthreads();
#pragma unroll
    for (int j = 0; j < 4; j++) {
        int n = n0 + ty + 8 * j;
        h162 v;
        v.x = __float2half_rn(t[2 * tx][ty + 8 * j]);
        v.y = __float2half_rn(t[2 * tx + 1][ty + 8 * j]);
        *(h162*)(Wh + (long)n * K + k0 + 2 * tx) = v;
    }
}

// ---------------- V transpose ----------------
__global__ void vtrans_kernel(const h16* __restrict__ sh, int ld, h16* __restrict__ th)
{
    __shared__ h16 a[32][33];
    int bz = blockIdx.z, s0 = blockIdx.x * 32, d0 = blockIdx.y * 32;
    int tx = threadIdx.x, ty = threadIdx.y;
#pragma unroll
    for (int j = 0; j < 4; j++)
        a[ty + 8 * j][tx] = sh[(long)(bz * S_ + s0 + ty + 8 * j) * ld + d0 + tx];
    __syncthreads();
#pragma unroll
    for (int j = 0; j < 4; j++)
        th[(long)(bz * D_ + d0 + ty + 8 * j) * S_ + s0 + tx] = a[tx][ty + 8 * j];
}

// ---------------- embed ----------------
__global__ void embed_kernel(const int* __restrict__ tok, const float* __restrict__ emb,
                             const float* __restrict__ pos, float* __restrict__ out)
{
    int i = blockIdx.x * blockDim.x + threadIdx.x;
    if (i >= TOK * D_) return;
    int d = i % D_, t = i / D_, s = t % S_;
    out[i] = emb[(long)tok[t] * D_ + d] + pos[(long)s * D_ + d];
}

// ---------------- layernorm -> fp16 ----------------
__global__ void __launch_bounds__(256) ln_kernel(const float* __restrict__ x,
    const float* __restrict__ g, const float* __restrict__ b, h16* __restrict__ oh)
{
    int row = blockIdx.x, tid = threadIdx.x;
    const float* xr = x + (long)row * D_;
    float v[3], lsum = 0.f, lsq = 0.f;
#pragma unroll
    for (int i = 0; i < 3; i++) {
        float t = xr[tid + i * 256];
        v[i] = t; lsum += t; lsq += t * t;
    }
    __shared__ float s1[256], s2[256];
    s1[tid] = lsum; s2[tid] = lsq; __syncthreads();
    for (int off = 128; off > 0; off >>= 1) {
        if (tid < off) { s1[tid] += s1[tid+off]; s2[tid] += s2[tid+off]; }
        __syncthreads();
    }
    float mean = s1[0] * (1.f / D_);
    float inv = rsqrtf(s2[0] * (1.f / D_) - mean * mean + EPSF);
#pragma unroll
    for (int i = 0; i < 3; i++) {
        int d = tid + i * 256;
        oh[(long)row * D_ + d] = __float2half_rn((v[i] - mean) * inv * g[d] + b[d]);
    }
}

// ---------------- softmax: single-pass, fp16 in-place, values register-resident ----------------
__global__ void __launch_bounds__(256) softmax_kernel(h16* __restrict__ att, int causal)
{
    long row = blockIdx.x;
    int q = (int)(row % S_), tid = threadIdx.x;
    h16* a = att + row * (long)S_;
    int n = causal ? (q + 1) : S_;
    int base = tid * 4;

    h162 p0 = *(h162*)(a + base);
    h162 p1 = *(h162*)(a + base + 2);
    float v[4] = {__half2float(p0.x), __half2float(p0.y),
                  __half2float(p1.x), __half2float(p1.y)};
#pragma unroll
    for (int i = 0; i < 4; i++)
        if (base + i >= n) v[i] = -1e30f;

    __shared__ float sh[256];
    float m = fmaxf(fmaxf(v[0], v[1]), fmaxf(v[2], v[3]));
    sh[tid] = m; __syncthreads();
    for (int off = 128; off > 0; off >>= 1) {
        if (tid < off) sh[tid] = fmaxf(sh[tid], sh[tid+off]);
        __syncthreads();
    }
    float M = sh[0]; __syncthreads();

#pragma unroll
    for (int i = 0; i < 4; i++) v[i] = __expf(v[i] - M);
    sh[tid] = v[0] + v[1] + v[2] + v[3]; __syncthreads();
    for (int off = 128; off > 0; off >>= 1) {
        if (tid < off) sh[tid] += sh[tid+off];
        __syncthreads();
    }
    float inv = 1.f / sh[0];

    h162 o0, o1;
    o0.x = __float2half_rn(v[0] * inv); o0.y = __float2half_rn(v[1] * inv);
    o1.x = __float2half_rn(v[2] * inv); o1.y = __float2half_rn(v[3] * inv);
    *(h162*)(a + base) = o0;
    *(h162*)(a + base + 2) = o1;
}

// =====================================================================
// mma.sync fp16 GEMM: 3-stage cp.async pipeline, one sync per k-chunk.
// A[M,K], B[N,K] fp16. CTA 128 thr, tile 128xBN_, warp 64x(BN_/2).
// flags: 2=relu, 4=causal block skip (QK), 8=causal K-trim (AV).
// =====================================================================
#define CPA16(dst, src) \
    asm volatile("cp.async.cg.shared.global [%0], [%1], 16;" :: "r"(dst), "l"(src))
#define LDSM4(r, addr) \
    asm volatile("ldmatrix.sync.aligned.m8n8.x4.shared.b16 {%0,%1,%2,%3}, [%4];" \
                 : "=r"((r)[0]), "=r"((r)[1]), "=r"((r)[2]), "=r"((r)[3]) : "r"(addr))
#define MMA4(c, a, b0, b1)                                                    \
    asm volatile("mma.sync.aligned.m16n8k16.row.col.f32.f16.f16.f32 "         \
                 "{%0,%1,%2,%3}, {%4,%5,%6,%7}, {%8,%9}, {%0,%1,%2,%3};"      \
                 : "+f"((c).x), "+f"((c).y), "+f"((c).z), "+f"((c).w)         \
                 : "r"((a)[0]), "r"((a)[1]), "r"((a)[2]), "r"((a)[3]),        \
                   "r"(b0), "r"(b1))

__device__ __forceinline__ unsigned pkh(float x, float y)
{
    h162 hb;
    hb.x = __float2half_rn(x); hb.y = __float2half_rn(y);
    return *reinterpret_cast<unsigned*>(&hb);
}

template<int BN_>
__global__ void __launch_bounds__(128, 2) gemm_tc(
    const h16* __restrict__ Ah, int lda, long sAb, long sA2,
    const h16* __restrict__ Bh, int ldb, long sBb, long sB2,
    const float* __restrict__ bias, const float* __restrict__ res,
    float* __restrict__ C, h16* __restrict__ Ch,
    int ldc, long sCb, long sC2, int K, int Nreal, float alpha, int flags)
{
    constexpr int ASE = 128 * 40;
    constexpr int BSE = BN_ * 40;
    constexpr int STE = ASE + BSE;
    constexpr int WN = BN_ / 2;
    constexpr int JB = WN / 8;
    extern __shared__ __align__(16) h16 sm[];

    int n0 = blockIdx.x * BN_;
    int m0 = blockIdx.y * 128;
    if ((flags & 4) && n0 >= m0 + 128) return;

    int z = blockIdx.z, zb = z / H_, zh = z % H_;
    Ah += (long)zb * sAb + (long)zh * sA2;
    Bh += (long)zb * sBb + (long)zh * sB2;
    long cOff = (long)zb * sCb + (long)zh * sC2;

    int tid = threadIdx.x, lane = tid & 31, wid = tid >> 5;
    int wm = wid & 1, wn = wid >> 1;
    int g = lane >> 2, tig = lane & 3;
    unsigned sbase = (unsigned)__cvta_generic_to_shared(sm);

    int Keff = (flags & 8) ? min(K, m0 + 128) : K;
    int nch = Keff >> 5;

    auto load_stage = [&](int st, int k0) {
        unsigned aH = sbase + (unsigned)st * STE * 2;
        unsigned bH = aH + ASE * 2;
#pragma unroll
        for (int i = 0; i < 4; i++) {
            int c = tid + i * 128, row = c >> 2, kg = c & 3;
            unsigned off = (unsigned)(row * 40 + kg * 8) * 2;
            CPA16(aH + off, Ah + (long)(m0 + row) * lda + k0 + kg * 8);
        }
#pragma unroll
        for (int i = 0; i < BN_ / 32; i++) {
            int c = tid + i * 128, row = c >> 2, kg = c & 3;
            unsigned off = (unsigned)(row * 40 + kg * 8) * 2;
            CPA16(bH + off, Bh + (long)(n0 + row) * ldb + k0 + kg * 8);
        }
        asm volatile("cp.async.commit_group;");
    };

    float4 acc[4][JB];
#pragma unroll
    for (int i = 0; i < 4; i++)
#pragma unroll
        for (int j = 0; j < JB; j++) acc[i][j] = make_float4(0.f, 0.f, 0.f, 0.f);

    int a_r = (lane & 7) + ((lane >> 3) & 1) * 8;
    int a_c8 = (lane >> 4) * 8;
    int bt_n = ((lane >> 4) << 3) + (lane & 7);
    int bt_k8 = ((lane >> 3) & 1) * 8;

    // 3-stage pipeline, lookahead 2
    load_stage(0, 0);
    if (nch > 1) load_stage(1, 32);

    for (int it = 0; it < nch; it++) {
        int st = it % 3;
        if (it + 1 < nch) asm volatile("cp.async.wait_group 1;");
        else              asm volatile("cp.async.wait_group 0;");
        __syncthreads();
        if (it + 2 < nch) load_stage((it + 2) % 3, (it + 2) * 32);

        unsigned aAh = sbase + (unsigned)st * STE * 2;
        unsigned aBh = aAh + ASE * 2;
#pragma unroll
        for (int ks = 0; ks < 2; ks++) {
            unsigned ah[4][4], bh[JB/2][4];
#pragma unroll
            for (int mi = 0; mi < 4; mi++) {
                unsigned off = (unsigned)(((wm * 64 + mi * 16 + a_r) * 40) + ks * 16 + a_c8) * 2;
                LDSM4(ah[mi], aAh + off);
            }
#pragma unroll
            for (int jp = 0; jp < JB/2; jp++) {
                unsigned off = (unsigned)(((wn * WN + jp * 16 + bt_n) * 40) + ks * 16 + bt_k8) * 2;
                LDSM4(bh[jp], aBh + off);
            }
#pragma unroll
            for (int mi = 0; mi < 4; mi++) {
#pragma unroll
                for (int j = 0; j < JB; j++) {
                    int jp = j >> 1, o = (j & 1) << 1;
                    MMA4(acc[mi][j], ah[mi], bh[jp][o], bh[jp][o + 1]);
                }
            }
        }
    }

    float* Cp = C ? C + cOff : nullptr;
    h16* Chp = Ch ? Ch + cOff : nullptr;
#pragma unroll
    for (int mi = 0; mi < 4; mi++) {
#pragma unroll
        for (int j = 0; j < JB; j++) {
            int col = n0 + wn * WN + j * 8 + tig * 2;
            if (col >= Nreal) continue;
            int row0 = m0 + wm * 64 + mi * 16 + g, row1 = row0 + 8;
            float4 a = acc[mi][j];
            float2 bb = bias ? *(const float2*)(bias + col) : make_float2(0.f, 0.f);
            float2 v0, v1;
            v0.x = a.x * alpha + bb.x; v0.y = a.y * alpha + bb.y;
            v1.x = a.z * alpha + bb.x; v1.y = a.w * alpha + bb.y;
            if (res) {
                float2 q0 = *(const float2*)(res + (long)row0 * ldc + col);
                float2 q1 = *(const float2*)(res + (long)row1 * ldc + col);
                v0.x += q0.x; v0.y += q0.y; v1.x += q1.x; v1.y += q1.y;
            }
            if (flags & 2) {
                v0.x = fmaxf(v0.x, 0.f); v0.y = fmaxf(v0.y, 0.f);
                v1.x = fmaxf(v1.x, 0.f); v1.y = fmaxf(v1.y, 0.f);
            }
            if (Cp) {
                *(float2*)(Cp + (long)row0 * ldc + col) = v0;
                *(float2*)(Cp + (long)row1 * ldc + col) = v1;
            }
            if (Chp) {
                *(unsigned*)(Chp + (long)row0 * ldc + col) = pkh(v0.x, v0.y);
                *(unsigned*)(Chp + (long)row1 * ldc + col) = pkh(v1.x, v1.y);
            }
        }
    }
}

#define SMEM128 (3 * (128*40 + 128*40) * 2)
#define SMEM64  (3 * (128*40 + 64*40) * 2)

template<int BN_>
static void runG(dim3 grid,
                 const h16* Ah, int lda, long sAb, long sA2,
                 const h16* Bh, int ldb, long sBb, long sB2,
                 const float* bias, const float* res,
                 float* C, h16* Ch, int ldc, long sCb, long sC2,
                 int K, int Nreal, float alpha, int flags)
{
    gemm_tc<BN_><<<grid, 128, BN_ == 128 ? SMEM128 : SMEM64>>>(
        Ah, lda, sAb, sA2, Bh, ldb, sBb, sB2,
        bias, res, C, Ch, ldc, sCb, sC2, K, Nreal, alpha, flags);
}

static void gemmW(const h16* Ah, int K, const h16* Bh, int N, int Nreal,
                  const float* bias, const float* res,
                  float* C, h16* Ch, int ldc, int relu)
{
    runG<128>(dim3(N / 128, TOK / 128, 1), Ah, K, 0, 0, Bh, K, 0, 0,
              bias, res, C, Ch, ldc, 0, 0, K, Nreal, 1.f, relu ? 2 : 0);
}

extern "C" void kernel_launch(void* const* d_in, const int* in_sizes, int n_in,
                              void* d_out, int out_size)
{
    (void)in_sizes; (void)n_in; (void)out_size;
    const int* src = (const int*)d_in[0];
    const int* target = (const int*)d_in[2];
    const float* src_emb = (const float*)d_in[4];
    const float* tgt_emb = (const float*)d_in[5];
    const float* pos_emb = (const float*)d_in[6];
    const float* eaw = (const float*)d_in[7];
    const float* eab = (const float*)d_in[8];
    const float* elg = (const float*)d_in[9];
    const float* elb = (const float*)d_in[10];
    const float* ef1 = (const float*)d_in[11];
    const float* eb1 = (const float*)d_in[12];
    const float* ef2 = (const float*)d_in[13];
    const float* eb2 = (const float*)d_in[14];
    const float* eng = (const float*)d_in[15];
    const float* enb = (const float*)d_in[16];
    const float* daw = (const float*)d_in[17];
    const float* dab = (const float*)d_in[18];
    const float* dlg = (const float*)d_in[19];
    const float* dlb = (const float*)d_in[20];
    const float* df1 = (const float*)d_in[21];
    const float* db1 = (const float*)d_in[22];
    const float* df2 = (const float*)d_in[23];
    const float* db2 = (const float*)d_in[24];
    const float* dng = (const float*)d_in[25];
    const float* dnb = (const float*)d_in[26];
    const float* ow = (const float*)d_in[27];
    const float* ob = (const float*)d_in[28];
    float* out = (float*)d_out;

    cudaFuncSetAttribute(gemm_tc<128>, cudaFuncAttributeMaxDynamicSharedMemorySize, SMEM128);
    cudaFuncSetAttribute(gemm_tc<64>, cudaFuncAttributeMaxDynamicSharedMemorySize, SMEM64);

    float* x;
    h16 *xn, *qkv, *cq, *o, *mem, *ffh, *ap, *vt;
    h16 *wea, *wda, *we1, *we2, *wd1, *wd2, *wo;
    cudaGetSymbolAddress((void**)&x, g_x);
    cudaGetSymbolAddress((void**)&xn, g_xn);
    cudaGetSymbolAddress((void**)&qkv, g_qkv);
    cudaGetSymbolAddress((void**)&cq, g_cq);
    cudaGetSymbolAddress((void**)&o, g_o);
    cudaGetSymbolAddress((void**)&mem, g_mem);
    cudaGetSymbolAddress((void**)&ffh, g_ffh);
    cudaGetSymbolAddress((void**)&ap, g_ap);
    cudaGetSymbolAddress((void**)&vt, g_vt);
    cudaGetSymbolAddress((void**)&wea, g_wea);
    cudaGetSymbolAddress((void**)&wda, g_wda);
    cudaGetSymbolAddress((void**)&we1, g_we1);
    cudaGetSymbolAddress((void**)&we2, g_we2);
    cudaGetSymbolAddress((void**)&wd1, g_wd1);
    cudaGetSymbolAddress((void**)&wd2, g_wd2);
    cudaGetSymbolAddress((void**)&wo, g_wo);

    dim3 tb(32, 8);
    ttrans_kernel<<<dim3(24, 12, L_*4), tb>>>(eaw, wea, D_, D_, D_);
    ttrans_kernel<<<dim3(24, 12, L_*8), tb>>>(daw, wda, D_, D_, D_);
    ttrans_kernel<<<dim3(96, 12, L_), tb>>>(ef1, we1, D_, FF_, FF_);
    ttrans_kernel<<<dim3(24, 48, L_), tb>>>(ef2, we2, FF_, D_, D_);
    ttrans_kernel<<<dim3(96, 12, L_), tb>>>(df1, wd1, D_, FF_, FF_);
    ttrans_kernel<<<dim3(24, 48, L_), tb>>>(df2, wd2, FF_, D_, D_);
    ttrans_kernel<<<dim3(VP/32, 12, 1), tb>>>(ow, wo, D_, V_, VP);

    const long DD = (long)D_ * D_;
    const long SS = (long)S_ * S_;
    const int nblk = (TOK * D_ + 255) / 256;

    auto attention = [&](const h16* qH, int ldq, long sqb,
                         const h16* kH, int ldk, long skb, int causal) {
        runG<128>(dim3(8, 8, B_ * H_),
                  qH, ldq, sqb, 64, kH, ldk, skb, 64,
                  nullptr, nullptr, nullptr, ap,
                  S_, (long)H_ * SS, SS, 64, S_, 0.125f, causal ? 4 : 0);
        softmax_kernel<<<B_ * H_ * S_, 256>>>(ap, causal);
        runG<64>(dim3(1, 8, B_ * H_),
                 ap, S_, (long)H_ * SS, SS,
                 vt, S_, (long)D_ * S_, (long)64 * S_,
                 nullptr, nullptr, nullptr, o,
                 D_, (long)S_ * D_, 64, S_, 64, 1.f, causal ? 8 : 0);
    };

    // ================= encoder =================
    embed_kernel<<<nblk, 256>>>(src, src_emb, pos_emb, x);
    for (int l = 0; l < L_; l++) {
        const h16* wh = wea + (long)l * 4 * DD;
        const float* bb = eab + (long)l * 4 * D_;
        ln_kernel<<<TOK, 256>>>(x, elg + (l*2)*D_, elb + (l*2)*D_, xn);
        gemmW(xn, D_, wh, QKV, QKV, bb, nullptr, nullptr, qkv, QKV, 0);
        vtrans_kernel<<<dim3(32, 24, B_), tb>>>(qkv + 1536, QKV, vt);
        attention(qkv, QKV, (long)S_ * QKV, qkv + 768, QKV, (long)S_ * QKV, 0);
        gemmW(o, D_, wh + 3*DD, D_, D_, bb + 3*D_, x, x, nullptr, D_, 0);
        ln_kernel<<<TOK, 256>>>(x, elg + (l*2+1)*D_, elb + (l*2+1)*D_, xn);
        gemmW(xn, D_, we1 + (long)l*FF_*D_, FF_, FF_, eb1 + l*FF_, nullptr, nullptr, ffh, FF_, 1);
        gemmW(ffh, FF_, we2 + (long)l*D_*FF_, D_, D_, eb2 + l*D_, x, x, nullptr, D_, 0);
    }
    ln_kernel<<<TOK, 256>>>(x, eng, enb, mem);

    // ================= decoder =================
    embed_kernel<<<nblk, 256>>>(target, tgt_emb, pos_emb, x);
    for (int l = 0; l < L_; l++) {
        const h16* wh = wda + (long)l * 8 * DD;
        const float* bb = dab + (long)l * 8 * D_;
        // causal self-attention (fused QKV)
        ln_kernel<<<TOK, 256>>>(x, dlg + (l*3)*D_, dlb + (l*3)*D_, xn);
        gemmW(xn, D_, wh, QKV, QKV, bb, nullptr, nullptr, qkv, QKV, 0);
        vtrans_kernel<<<dim3(32, 24, B_), tb>>>(qkv + 1536, QKV, vt);
        attention(qkv, QKV, (long)S_ * QKV, qkv + 768, QKV, (long)S_ * QKV, 1);
        gemmW(o, D_, wh + 3*DD, D_, D_, bb + 3*D_, x, x, nullptr, D_, 0);
        // cross-attention (fused KV from mem)
        ln_kernel<<<TOK, 256>>>(x, dlg + (l*3+1)*D_, dlb + (l*3+1)*D_, xn);
        gemmW(xn, D_, wh + 4*DD, D_, D_, bb + 4*D_, nullptr, nullptr, cq, D_, 0);
        gemmW(mem, D_, wh + 5*DD, 2*D_, 2*D_, bb + 5*D_, nullptr, nullptr, qkv, 2*D_, 0);
        vtrans_kernel<<<dim3(32, 24, B_), tb>>>(qkv + 768, 2*D_, vt);
        attention(cq, D_, (long)S_ * D_, qkv, 2*D_, (long)S_ * 2 * D_, 0);
        gemmW(o, D_, wh + 7*DD, D_, D_, bb + 7*D_, x, x, nullptr, D_, 0);
        // FFN
        ln_kernel<<<TOK, 256>>>(x, dlg + (l*3+2)*D_, dlb + (l*3+2)*D_, xn);
        gemmW(xn, D_, wd1 + (long)l*FF_*D_, FF_, FF_, db1 + l*FF_, nullptr, nullptr, ffh, FF_, 1);
        gemmW(ffh, FF_, wd2 + (long)l*D_*FF_, D_, D_, db2 + l*D_, x, x, nullptr, D_, 0);
    }
    ln_kernel<<<TOK, 256>>>(x, dng, dnb, xn);

    // ================= output projection =================
    gemmW(xn, D_, wo, VP, V_, ob, nullptr, out, nullptr, V_, 0);
}

// round 12
// speedup vs baseline: 1.1147x; 1.1147x over previous
#include <cuda_runtime.h>
#include <cuda_fp16.h>
#include <cstdint>

#define B_ 4
#define S_ 1024
#define D_ 768
#define H_ 12
#define L_ 4
#define V_ 8000
#define VP 8064
#define FF_ 3072
#define TOK 4096
#define QKV 2304
#define EPSF 1e-5f
typedef __half h16;
typedef __half2 h162;

// ---------------- scratch ----------------
__device__ float g_x[TOK * D_];
__device__ h16 g_xn[TOK * D_];
__device__ h16 g_qkv[TOK * QKV];
__device__ h16 g_cq[TOK * D_];
__device__ h16 g_o[TOK * D_];
__device__ h16 g_mem[TOK * D_];
__device__ h16 g_ffh[TOK * FF_];
__device__ h16 g_ap[(long)B_ * H_ * S_ * S_];
__device__ h16 g_vt[(long)B_ * D_ * S_];
__device__ h16 g_wea[L_*4*D_*D_];
__device__ h16 g_wda[L_*8*D_*D_];
__device__ h16 g_we1[L_*FF_*D_];
__device__ h16 g_we2[L_*D_*FF_];
__device__ h16 g_wd1[L_*FF_*D_];
__device__ h16 g_wd2[L_*D_*FF_];
__device__ h16 g_wo[(long)VP * D_];

// ---------------- transpose+convert: slice z of W[K,N] fp32 -> [Npad,K] fp16 ----------------
// 64k x 32n tiles, vectorized h162 writes (verified faster in R10 ncu).
__global__ void ttrans_kernel(const float* __restrict__ W, h16* __restrict__ Wh,
                              int K, int N, int Npad)
{
    __shared__ float t[64][33];
    int z = blockIdx.z;
    W += (long)z * K * N; Wh += (long)z * Npad * K;
    int n0 = blockIdx.x * 32, k0 = blockIdx.y * 64;
    int tx = threadIdx.x, ty = threadIdx.y;   // 32 x 8
#pragma unroll
    for (int j = 0; j < 8; j++) {
        int k = k0 + ty + 8 * j, n = n0 + tx;
        t[ty + 8 * j][tx] = (n < N) ? W[(long)k * N + n] : 0.f;
    }
    __syncthreads();
#pragma unroll
    for (int j = 0; j < 4; j++) {
        int n = n0 + ty + 8 * j;
        h162 v;
        v.x = __float2half_rn(t[2 * tx][ty + 8 * j]);
        v.y = __float2half_rn(t[2 * tx + 1][ty + 8 * j]);
        *(h162*)(Wh + (long)n * K + k0 + 2 * tx) = v;
    }
}

// ---------------- V transpose ----------------
__global__ void vtrans_kernel(const h16* __restrict__ sh, int ld, h16* __restrict__ th)
{
    __shared__ h16 a[32][33];
    int bz = blockIdx.z, s0 = blockIdx.x * 32, d0 = blockIdx.y * 32;
    int tx = threadIdx.x, ty = threadIdx.y;
#pragma unroll
    for (int j = 0; j < 4; j++)
        a[ty + 8 * j][tx] = sh[(long)(bz * S_ + s0 + ty + 8 * j) * ld + d0 + tx];
    __syncthreads();
#pragma unroll
    for (int j = 0; j < 4; j++)
        th[(long)(bz * D_ + d0 + ty + 8 * j) * S_ + s0 + tx] = a[tx][ty + 8 * j];
}

// ---------------- embed ----------------
__global__ void embed_kernel(const int* __restrict__ tok, const float* __restrict__ emb,
                             const float* __restrict__ pos, float* __restrict__ out)
{
    int i = blockIdx.x * blockDim.x + threadIdx.x;
    if (i >= TOK * D_) return;
    int d = i % D_, t = i / D_, s = t % S_;
    out[i] = emb[(long)tok[t] * D_ + d] + pos[(long)s * D_ + d];
}

// ---------------- layernorm -> fp16 ----------------
__global__ void __launch_bounds__(256) ln_kernel(const float* __restrict__ x,
    const float* __restrict__ g, const float* __restrict__ b, h16* __restrict__ oh)
{
    int row = blockIdx.x, tid = threadIdx.x;
    const float* xr = x + (long)row * D_;
    float v[3], lsum = 0.f, lsq = 0.f;
#pragma unroll
    for (int i = 0; i < 3; i++) {
        float t = xr[tid + i * 256];
        v[i] = t; lsum += t; lsq += t * t;
    }
    __shared__ float s1[256], s2[256];
    s1[tid] = lsum; s2[tid] = lsq; __syncthreads();
    for (int off = 128; off > 0; off >>= 1) {
        if (tid < off) { s1[tid] += s1[tid+off]; s2[tid] += s2[tid+off]; }
        __syncthreads();
    }
    float mean = s1[0] * (1.f / D_);
    float inv = rsqrtf(s2[0] * (1.f / D_) - mean * mean + EPSF);
#pragma unroll
    for (int i = 0; i < 3; i++) {
        int d = tid + i * 256;
        oh[(long)row * D_ + d] = __float2half_rn((v[i] - mean) * inv * g[d] + b[d]);
    }
}

// ---------------- softmax: single-pass, fp16 in-place, register-resident ----------------
__global__ void __launch_bounds__(256) softmax_kernel(h16* __restrict__ att, int causal)
{
    long row = blockIdx.x;
    int q = (int)(row % S_), tid = threadIdx.x;
    h16* a = att + row * (long)S_;
    int n = causal ? (q + 1) : S_;
    int base = tid * 4;

    h162 p0 = *(h162*)(a + base);
    h162 p1 = *(h162*)(a + base + 2);
    float v[4] = {__half2float(p0.x), __half2float(p0.y),
                  __half2float(p1.x), __half2float(p1.y)};
#pragma unroll
    for (int i = 0; i < 4; i++)
        if (base + i >= n) v[i] = -1e30f;

    __shared__ float sh[256];
    float m = fmaxf(fmaxf(v[0], v[1]), fmaxf(v[2], v[3]));
    sh[tid] = m; __syncthreads();
    for (int off = 128; off > 0; off >>= 1) {
        if (tid < off) sh[tid] = fmaxf(sh[tid], sh[tid+off]);
        __syncthreads();
    }
    float M = sh[0]; __syncthreads();

#pragma unroll
    for (int i = 0; i < 4; i++) v[i] = __expf(v[i] - M);
    sh[tid] = v[0] + v[1] + v[2] + v[3]; __syncthreads();
    for (int off = 128; off > 0; off >>= 1) {
        if (tid < off) sh[tid] += sh[tid+off];
        __syncthreads();
    }
    float inv = 1.f / sh[0];

    h162 o0, o1;
    o0.x = __float2half_rn(v[0] * inv); o0.y = __float2half_rn(v[1] * inv);
    o1.x = __float2half_rn(v[2] * inv); o1.y = __float2half_rn(v[3] * inv);
    *(h162*)(a + base) = o0;
    *(h162*)(a + base + 2) = o1;
}

// =====================================================================
// mma.sync fp16 GEMM — R9 2-stage pipeline (proven fastest).
// A[M,K], B[N,K] fp16. CTA 128 thr, tile 128xBN_, warp 64x(BN_/2).
// flags: 2=relu, 4=causal block skip (QK), 8=causal K-trim (AV).
// =====================================================================
#define CPA16(dst, src) \
    asm volatile("cp.async.cg.shared.global [%0], [%1], 16;" :: "r"(dst), "l"(src))
#define LDSM4(r, addr) \
    asm volatile("ldmatrix.sync.aligned.m8n8.x4.shared.b16 {%0,%1,%2,%3}, [%4];" \
                 : "=r"((r)[0]), "=r"((r)[1]), "=r"((r)[2]), "=r"((r)[3]) : "r"(addr))
#define MMA4(c, a, b0, b1)                                                    \
    asm volatile("mma.sync.aligned.m16n8k16.row.col.f32.f16.f16.f32 "         \
                 "{%0,%1,%2,%3}, {%4,%5,%6,%7}, {%8,%9}, {%0,%1,%2,%3};"      \
                 : "+f"((c).x), "+f"((c).y), "+f"((c).z), "+f"((c).w)         \
                 : "r"((a)[0]), "r"((a)[1]), "r"((a)[2]), "r"((a)[3]),        \
                   "r"(b0), "r"(b1))

__device__ __forceinline__ unsigned pkh(float x, float y)
{
    h162 hb;
    hb.x = __float2half_rn(x); hb.y = __float2half_rn(y);
    return *reinterpret_cast<unsigned*>(&hb);
}

template<int BN_>
__global__ void __launch_bounds__(128, 2) gemm_tc(
    const h16* __restrict__ Ah, int lda, long sAb, long sA2,
    const h16* __restrict__ Bh, int ldb, long sBb, long sB2,
    const float* __restrict__ bias, const float* __restrict__ res,
    float* __restrict__ C, h16* __restrict__ Ch,
    int ldc, long sCb, long sC2, int K, int Nreal, float alpha, int flags)
{
    constexpr int ASE = 128 * 40;
    constexpr int BSE = BN_ * 40;
    constexpr int STE = ASE + BSE;
    constexpr int WN = BN_ / 2;
    constexpr int JB = WN / 8;
    extern __shared__ __align__(16) h16 sm[];

    int n0 = blockIdx.x * BN_;
    int m0 = blockIdx.y * 128;
    if ((flags & 4) && n0 >= m0 + 128) return;

    int z = blockIdx.z, zb = z / H_, zh = z % H_;
    Ah += (long)zb * sAb + (long)zh * sA2;
    Bh += (long)zb * sBb + (long)zh * sB2;
    long cOff = (long)zb * sCb + (long)zh * sC2;

    int tid = threadIdx.x, lane = tid & 31, wid = tid >> 5;
    int wm = wid & 1, wn = wid >> 1;
    int g = lane >> 2, tig = lane & 3;
    unsigned sbase = (unsigned)__cvta_generic_to_shared(sm);

    int Keff = (flags & 8) ? min(K, m0 + 128) : K;
    int nch = Keff >> 5;

    auto load_stage = [&](int st, int k0) {
        unsigned aH = sbase + (unsigned)st * STE * 2;
        unsigned bH = aH + ASE * 2;
#pragma unroll
        for (int i = 0; i < 4; i++) {
            int c = tid + i * 128, row = c >> 2, kg = c & 3;
            unsigned off = (unsigned)(row * 40 + kg * 8) * 2;
            CPA16(aH + off, Ah + (long)(m0 + row) * lda + k0 + kg * 8);
        }
#pragma unroll
        for (int i = 0; i < BN_ / 32; i++) {
            int c = tid + i * 128, row = c >> 2, kg = c & 3;
            unsigned off = (unsigned)(row * 40 + kg * 8) * 2;
            CPA16(bH + off, Bh + (long)(n0 + row) * ldb + k0 + kg * 8);
        }
        asm volatile("cp.async.commit_group;");
    };

    float4 acc[4][JB];
#pragma unroll
    for (int i = 0; i < 4; i++)
#pragma unroll
        for (int j = 0; j < JB; j++) acc[i][j] = make_float4(0.f, 0.f, 0.f, 0.f);

    int a_r = (lane & 7) + ((lane >> 3) & 1) * 8;
    int a_c8 = (lane >> 4) * 8;
    int bt_n = ((lane >> 4) << 3) + (lane & 7);
    int bt_k8 = ((lane >> 3) & 1) * 8;

    load_stage(0, 0);
    for (int it = 0; it < nch; it++) {
        int st = it & 1;
        if (it + 1 < nch) {
            load_stage(st ^ 1, (it + 1) * 32);
            asm volatile("cp.async.wait_group 1;");
        } else {
            asm volatile("cp.async.wait_group 0;");
        }
        __syncthreads();
        unsigned aAh = sbase + (unsigned)st * STE * 2;
        unsigned aBh = aAh + ASE * 2;
#pragma unroll
        for (int ks = 0; ks < 2; ks++) {
            unsigned ah[4][4], bh[JB/2][4];
#pragma unroll
            for (int mi = 0; mi < 4; mi++) {
                unsigned off = (unsigned)(((wm * 64 + mi * 16 + a_r) * 40) + ks * 16 + a_c8) * 2;
                LDSM4(ah[mi], aAh + off);
            }
#pragma unroll
            for (int jp = 0; jp < JB/2; jp++) {
                unsigned off = (unsigned)(((wn * WN + jp * 16 + bt_n) * 40) + ks * 16 + bt_k8) * 2;
                LDSM4(bh[jp], aBh + off);
            }
#pragma unroll
            for (int mi = 0; mi < 4; mi++) {
#pragma unroll
                for (int j = 0; j < JB; j++) {
                    int jp = j >> 1, o = (j & 1) << 1;
                    MMA4(acc[mi][j], ah[mi], bh[jp][o], bh[jp][o + 1]);
                }
            }
        }
        __syncthreads();
    }

    float* Cp = C ? C + cOff : nullptr;
    h16* Chp = Ch ? Ch + cOff : nullptr;
#pragma unroll
    for (int mi = 0; mi < 4; mi++) {
#pragma unroll
        for (int j = 0; j < JB; j++) {
            int col = n0 + wn * WN + j * 8 + tig * 2;
            if (col >= Nreal) continue;
            int row0 = m0 + wm * 64 + mi * 16 + g, row1 = row0 + 8;
            float4 a = acc[mi][j];
            float2 bb = bias ? *(const float2*)(bias + col) : make_float2(0.f, 0.f);
            float2 v0, v1;
            v0.x = a.x * alpha + bb.x; v0.y = a.y * alpha + bb.y;
            v1.x = a.z * alpha + bb.x; v1.y = a.w * alpha + bb.y;
            if (res) {
                float2 q0 = *(const float2*)(res + (long)row0 * ldc + col);
                float2 q1 = *(const float2*)(res + (long)row1 * ldc + col);
                v0.x += q0.x; v0.y += q0.y; v1.x += q1.x; v1.y += q1.y;
            }
            if (flags & 2) {
                v0.x = fmaxf(v0.x, 0.f); v0.y = fmaxf(v0.y, 0.f);
                v1.x = fmaxf(v1.x, 0.f); v1.y = fmaxf(v1.y, 0.f);
            }
            if (Cp) {
                *(float2*)(Cp + (long)row0 * ldc + col) = v0;
                *(float2*)(Cp + (long)row1 * ldc + col) = v1;
            }
            if (Chp) {
                *(unsigned*)(Chp + (long)row0 * ldc + col) = pkh(v0.x, v0.y);
                *(unsigned*)(Chp + (long)row1 * ldc + col) = pkh(v1.x, v1.y);
            }
        }
    }
}

#define SMEM128 (2 * (128*40 + 128*40) * 2)
#define SMEM64  (2 * (128*40 + 64*40) * 2)

template<int BN_>
static void runG(dim3 grid,
                 const h16* Ah, int lda, long sAb, long sA2,
                 const h16* Bh, int ldb, long sBb, long sB2,
                 const float* bias, const float* res,
                 float* C, h16* Ch, int ldc, long sCb, long sC2,
                 int K, int Nreal, float alpha, int flags)
{
    gemm_tc<BN_><<<grid, 128, BN_ == 128 ? SMEM128 : SMEM64>>>(
        Ah, lda, sAb, sA2, Bh, ldb, sBb, sB2,
        bias, res, C, Ch, ldc, sCb, sC2, K, Nreal, alpha, flags);
}

static void gemmW(const h16* Ah, int K, const h16* Bh, int N, int Nreal,
                  const float* bias, const float* res,
                  float* C, h16* Ch, int ldc, int relu)
{
    runG<128>(dim3(N / 128, TOK / 128, 1), Ah, K, 0, 0, Bh, K, 0, 0,
              bias, res, C, Ch, ldc, 0, 0, K, Nreal, 1.f, relu ? 2 : 0);
}

extern "C" void kernel_launch(void* const* d_in, const int* in_sizes, int n_in,
                              void* d_out, int out_size)
{
    (void)in_sizes; (void)n_in; (void)out_size;
    const int* src = (const int*)d_in[0];
    const int* target = (const int*)d_in[2];
    const float* src_emb = (const float*)d_in[4];
    const float* tgt_emb = (const float*)d_in[5];
    const float* pos_emb = (const float*)d_in[6];
    const float* eaw = (const float*)d_in[7];
    const float* eab = (const float*)d_in[8];
    const float* elg = (const float*)d_in[9];
    const float* elb = (const float*)d_in[10];
    const float* ef1 = (const float*)d_in[11];
    const float* eb1 = (const float*)d_in[12];
    const float* ef2 = (const float*)d_in[13];
    const float* eb2 = (const float*)d_in[14];
    const float* eng = (const float*)d_in[15];
    const float* enb = (const float*)d_in[16];
    const float* daw = (const float*)d_in[17];
    const float* dab = (const float*)d_in[18];
    const float* dlg = (const float*)d_in[19];
    const float* dlb = (const float*)d_in[20];
    const float* df1 = (const float*)d_in[21];
    const float* db1 = (const float*)d_in[22];
    const float* df2 = (const float*)d_in[23];
    const float* db2 = (const float*)d_in[24];
    const float* dng = (const float*)d_in[25];
    const float* dnb = (const float*)d_in[26];
    const float* ow = (const float*)d_in[27];
    const float* ob = (const float*)d_in[28];
    float* out = (float*)d_out;

    cudaFuncSetAttribute(gemm_tc<128>, cudaFuncAttributeMaxDynamicSharedMemorySize, SMEM128);
    cudaFuncSetAttribute(gemm_tc<64>, cudaFuncAttributeMaxDynamicSharedMemorySize, SMEM64);

    float* x;
    h16 *xn, *qkv, *cq, *o, *mem, *ffh, *ap, *vt;
    h16 *wea, *wda, *we1, *we2, *wd1, *wd2, *wo;
    cudaGetSymbolAddress((void**)&x, g_x);
    cudaGetSymbolAddress((void**)&xn, g_xn);
    cudaGetSymbolAddress((void**)&qkv, g_qkv);
    cudaGetSymbolAddress((void**)&cq, g_cq);
    cudaGetSymbolAddress((void**)&o, g_o);
    cudaGetSymbolAddress((void**)&mem, g_mem);
    cudaGetSymbolAddress((void**)&ffh, g_ffh);
    cudaGetSymbolAddress((void**)&ap, g_ap);
    cudaGetSymbolAddress((void**)&vt, g_vt);
    cudaGetSymbolAddress((void**)&wea, g_wea);
    cudaGetSymbolAddress((void**)&wda, g_wda);
    cudaGetSymbolAddress((void**)&we1, g_we1);
    cudaGetSymbolAddress((void**)&we2, g_we2);
    cudaGetSymbolAddress((void**)&wd1, g_wd1);
    cudaGetSymbolAddress((void**)&wd2, g_wd2);
    cudaGetSymbolAddress((void**)&wo, g_wo);

    dim3 tb(32, 8);
    ttrans_kernel<<<dim3(24, 12, L_*4), tb>>>(eaw, wea, D_, D_, D_);
    ttrans_kernel<<<dim3(24, 12, L_*8), tb>>>(daw, wda, D_, D_, D_);
    ttrans_kernel<<<dim3(96, 12, L_), tb>>>(ef1, we1, D_, FF_, FF_);
    ttrans_kernel<<<dim3(24, 48, L_), tb>>>(ef2, we2, FF_, D_, D_);
    ttrans_kernel<<<dim3(96, 12, L_), tb>>>(df1, wd1, D_, FF_, FF_);
    ttrans_kernel<<<dim3(24, 48, L_), tb>>>(df2, wd2, FF_, D_, D_);
    ttrans_kernel<<<dim3(VP/32, 12, 1), tb>>>(ow, wo, D_, V_, VP);

    const long DD = (long)D_ * D_;
    const long SS = (long)S_ * S_;
    const int nblk = (TOK * D_ + 255) / 256;

    auto attention = [&](const h16* qH, int ldq, long sqb,
                         const h16* kH, int ldk, long skb, int causal) {
        runG<128>(dim3(8, 8, B_ * H_),
                  qH, ldq, sqb, 64, kH, ldk, skb, 64,
                  nullptr, nullptr, nullptr, ap,
                  S_, (long)H_ * SS, SS, 64, S_, 0.125f, causal ? 4 : 0);
        softmax_kernel<<<B_ * H_ * S_, 256>>>(ap, causal);
        runG<64>(dim3(1, 8, B_ * H_),
                 ap, S_, (long)H_ * SS, SS,
                 vt, S_, (long)D_ * S_, (long)64 * S_,
                 nullptr, nullptr, nullptr, o,
                 D_, (long)S_ * D_, 64, S_, 64, 1.f, causal ? 8 : 0);
    };

    // ================= encoder =================
    embed_kernel<<<nblk, 256>>>(src, src_emb, pos_emb, x);
    for (int l = 0; l < L_; l++) {
        const h16* wh = wea + (long)l * 4 * DD;
        const float* bb = eab + (long)l * 4 * D_;
        ln_kernel<<<TOK, 256>>>(x, elg + (l*2)*D_, elb + (l*2)*D_, xn);
        gemmW(xn, D_, wh, QKV, QKV, bb, nullptr, nullptr, qkv, QKV, 0);
        vtrans_kernel<<<dim3(32, 24, B_), tb>>>(qkv + 1536, QKV, vt);
        attention(qkv, QKV, (long)S_ * QKV, qkv + 768, QKV, (long)S_ * QKV, 0);
        gemmW(o, D_, wh + 3*DD, D_, D_, bb + 3*D_, x, x, nullptr, D_, 0);
        ln_kernel<<<TOK, 256>>>(x, elg + (l*2+1)*D_, elb + (l*2+1)*D_, xn);
        gemmW(xn, D_, we1 + (long)l*FF_*D_, FF_, FF_, eb1 + l*FF_, nullptr, nullptr, ffh, FF_, 1);
        gemmW(ffh, FF_, we2 + (long)l*D_*FF_, D_, D_, eb2 + l*D_, x, x, nullptr, D_, 0);
    }
    ln_kernel<<<TOK, 256>>>(x, eng, enb, mem);

    // ================= decoder =================
    embed_kernel<<<nblk, 256>>>(target, tgt_emb, pos_emb, x);
    for (int l = 0; l < L_; l++) {
        const h16* wh = wda + (long)l * 8 * DD;
        const float* bb = dab + (long)l * 8 * D_;
        // causal self-attention (fused QKV)
        ln_kernel<<<TOK, 256>>>(x, dlg + (l*3)*D_, dlb + (l*3)*D_, xn);
        gemmW(xn, D_, wh, QKV, QKV, bb, nullptr, nullptr, qkv, QKV, 0);
        vtrans_kernel<<<dim3(32, 24, B_), tb>>>(qkv + 1536, QKV, vt);
        attention(qkv, QKV, (long)S_ * QKV, qkv + 768, QKV, (long)S_ * QKV, 1);
        gemmW(o, D_, wh + 3*DD, D_, D_, bb + 3*D_, x, x, nullptr, D_, 0);
        // cross-attention (fused KV from mem)
        ln_kernel<<<TOK, 256>>>(x, dlg + (l*3+1)*D_, dlb + (l*3+1)*D_, xn);
        gemmW(xn, D_, wh + 4*DD, D_, D_, bb + 4*D_, nullptr, nullptr, cq, D_, 0);
        gemmW(mem, D_, wh + 5*DD, 2*D_, 2*D_, bb + 5*D_, nullptr, nullptr, qkv, 2*D_, 0);
        vtrans_kernel<<<dim3(32, 24, B_), tb>>>(qkv + 768, 2*D_, vt);
        attention(cq, D_, (long)S_ * D_, qkv, 2*D_, (long)S_ * 2 * D_, 0);
        gemmW(o, D_, wh + 7*DD, D_, D_, bb + 7*D_, x, x, nullptr, D_, 0);
        // FFN
        ln_kernel<<<TOK, 256>>>(x, dlg + (l*3+2)*D_, dlb + (l*3+2)*D_, xn);
        gemmW(xn, D_, wd1 + (long)l*FF_*D_, FF_, FF_, db1 + l*FF_, nullptr, nullptr, ffh, FF_, 1);
        gemmW(ffh, FF_, wd2 + (long)l*D_*FF_, D_, D_, db2 + l*D_, x, x, nullptr, D_, 0);
    }
    ln_kernel<<<TOK, 256>>>(x, dng, dnb, xn);

    // ================= output projection =================
    gemmW(xn, D_, wo, VP, V_, ob, nullptr, out, nullptr, V_, 0);
}

// round 13
// speedup vs baseline: 1.1287x; 1.0126x over previous
#include <cuda_runtime.h>
#include <cuda_fp16.h>
#include <cstdint>

#define B_ 4
#define S_ 1024
#define D_ 768
#define H_ 12
#define L_ 4
#define V_ 8000
#define VP 8064
#define FF_ 3072
#define TOK 4096
#define QKV 2304
#define EPSF 1e-5f
typedef __half h16;
typedef __half2 h162;

// ---------------- scratch ----------------
__device__ float g_x[TOK * D_];
__device__ h16 g_xn[TOK * D_];
__device__ h16 g_qkv[TOK * QKV];
__device__ h16 g_cq[TOK * D_];
__device__ h16 g_o[TOK * D_];
__device__ h16 g_mem[TOK * D_];
__device__ h16 g_ffh[TOK * FF_];
__device__ h16 g_ap[(long)B_ * H_ * S_ * S_];
__device__ h16 g_wea[L_*4*D_*D_];
__device__ h16 g_wda[L_*8*D_*D_];
__device__ h16 g_we1[L_*FF_*D_];
__device__ h16 g_we2[L_*D_*FF_];
__device__ h16 g_wd1[L_*FF_*D_];
__device__ h16 g_wd2[L_*D_*FF_];
__device__ h16 g_wo[(long)VP * D_];

// ---------------- transpose+convert: slice z of W[K,N] fp32 -> [Npad,K] fp16 ----------------
__global__ void ttrans_kernel(const float* __restrict__ W, h16* __restrict__ Wh,
                              int K, int N, int Npad)
{
    __shared__ float t[64][33];
    int z = blockIdx.z;
    W += (long)z * K * N; Wh += (long)z * Npad * K;
    int n0 = blockIdx.x * 32, k0 = blockIdx.y * 64;
    int tx = threadIdx.x, ty = threadIdx.y;   // 32 x 8
#pragma unroll
    for (int j = 0; j < 8; j++) {
        int k = k0 + ty + 8 * j, n = n0 + tx;
        t[ty + 8 * j][tx] = (n < N) ? W[(long)k * N + n] : 0.f;
    }
    __syncthreads();
#pragma unroll
    for (int j = 0; j < 4; j++) {
        int n = n0 + ty + 8 * j;
        h162 v;
        v.x = __float2half_rn(t[2 * tx][ty + 8 * j]);
        v.y = __float2half_rn(t[2 * tx + 1][ty + 8 * j]);
        *(h162*)(Wh + (long)n * K + k0 + 2 * tx) = v;
    }
}

// ---------------- embed ----------------
__global__ void embed_kernel(const int* __restrict__ tok, const float* __restrict__ emb,
                             const float* __restrict__ pos, float* __restrict__ out)
{
    int i = blockIdx.x * blockDim.x + threadIdx.x;
    if (i >= TOK * D_) return;
    int d = i % D_, t = i / D_, s = t % S_;
    out[i] = emb[(long)tok[t] * D_ + d] + pos[(long)s * D_ + d];
}

// ---------------- layernorm -> fp16 (warp-shuffle reduction) ----------------
__global__ void __launch_bounds__(256) ln_kernel(const float* __restrict__ x,
    const float* __restrict__ g, const float* __restrict__ b, h16* __restrict__ oh)
{
    int row = blockIdx.x, tid = threadIdx.x;
    int lane = tid & 31, wid = tid >> 5;
    const float* xr = x + (long)row * D_;
    float v[3], lsum = 0.f, lsq = 0.f;
#pragma unroll
    for (int i = 0; i < 3; i++) {
        float t = xr[tid + i * 256];
        v[i] = t; lsum += t; lsq += t * t;
    }
#pragma unroll
    for (int off = 16; off > 0; off >>= 1) {
        lsum += __shfl_xor_sync(0xffffffffu, lsum, off);
        lsq  += __shfl_xor_sync(0xffffffffu, lsq, off);
    }
    __shared__ float w1[8], w2[8];
    if (lane == 0) { w1[wid] = lsum; w2[wid] = lsq; }
    __syncthreads();
    float ts = 0.f, tq = 0.f;
#pragma unroll
    for (int i = 0; i < 8; i++) { ts += w1[i]; tq += w2[i]; }
    float mean = ts * (1.f / D_);
    float inv = rsqrtf(tq * (1.f / D_) - mean * mean + EPSF);
#pragma unroll
    for (int i = 0; i < 3; i++) {
        int d = tid + i * 256;
        oh[(long)row * D_ + d] = __float2half_rn((v[i] - mean) * inv * g[d] + b[d]);
    }
}

// ---------------- softmax: single-pass, fp16 in-place, register-resident ----------------
__global__ void __launch_bounds__(256) softmax_kernel(h16* __restrict__ att, int causal)
{
    long row = blockIdx.x;
    int q = (int)(row % S_), tid = threadIdx.x;
    h16* a = att + row * (long)S_;
    int n = causal ? (q + 1) : S_;
    int base = tid * 4;

    h162 p0 = *(h162*)(a + base);
    h162 p1 = *(h162*)(a + base + 2);
    float v[4] = {__half2float(p0.x), __half2float(p0.y),
                  __half2float(p1.x), __half2float(p1.y)};
#pragma unroll
    for (int i = 0; i < 4; i++)
        if (base + i >= n) v[i] = -1e30f;

    __shared__ float sh[256];
    float m = fmaxf(fmaxf(v[0], v[1]), fmaxf(v[2], v[3]));
    sh[tid] = m; __syncthreads();
    for (int off = 128; off > 0; off >>= 1) {
        if (tid < off) sh[tid] = fmaxf(sh[tid], sh[tid+off]);
        __syncthreads();
    }
    float M = sh[0]; __syncthreads();

#pragma unroll
    for (int i = 0; i < 4; i++) v[i] = __expf(v[i] - M);
    sh[tid] = v[0] + v[1] + v[2] + v[3]; __syncthreads();
    for (int off = 128; off > 0; off >>= 1) {
        if (tid < off) sh[tid] += sh[tid+off];
        __syncthreads();
    }
    float inv = 1.f / sh[0];

    h162 o0, o1;
    o0.x = __float2half_rn(v[0] * inv); o0.y = __float2half_rn(v[1] * inv);
    o1.x = __float2half_rn(v[2] * inv); o1.y = __float2half_rn(v[3] * inv);
    *(h162*)(a + base) = o0;
    *(h162*)(a + base + 2) = o1;
}

// =====================================================================
// mma.sync fp16 GEMM — 2-stage pipeline, BK=64.
// A[M,K]; B: TRB=0 -> [N,K] K-major, TRB=1 -> [K,N] (direct V, ldmatrix.trans).
// flags: 2=relu, 4=causal block skip (QK), 8=causal K-trim (AV).
// =====================================================================
#define CPA16(dst, src) \
    asm volatile("cp.async.cg.shared.global [%0], [%1], 16;" :: "r"(dst), "l"(src))
#define LDSM4(r, addr) \
    asm volatile("ldmatrix.sync.aligned.m8n8.x4.shared.b16 {%0,%1,%2,%3}, [%4];" \
                 : "=r"((r)[0]), "=r"((r)[1]), "=r"((r)[2]), "=r"((r)[3]) : "r"(addr))
#define LDSM4T(r, addr) \
    asm volatile("ldmatrix.sync.aligned.m8n8.x4.trans.shared.b16 {%0,%1,%2,%3}, [%4];" \
                 : "=r"((r)[0]), "=r"((r)[1]), "=r"((r)[2]), "=r"((r)[3]) : "r"(addr))
#define MMA4(c, a, b0, b1)                                                    \
    asm volatile("mma.sync.aligned.m16n8k16.row.col.f32.f16.f16.f32 "         \
                 "{%0,%1,%2,%3}, {%4,%5,%6,%7}, {%8,%9}, {%0,%1,%2,%3};"      \
                 : "+f"((c).x), "+f"((c).y), "+f"((c).z), "+f"((c).w)         \
                 : "r"((a)[0]), "r"((a)[1]), "r"((a)[2]), "r"((a)[3]),        \
                   "r"(b0), "r"(b1))

__device__ __forceinline__ unsigned pkh(float x, float y)
{
    h162 hb;
    hb.x = __float2half_rn(x); hb.y = __float2half_rn(y);
    return *reinterpret_cast<unsigned*>(&hb);
}

template<int BN_, int TRB>
__global__ void __launch_bounds__(128, 2) gemm_tc(
    const h16* __restrict__ Ah, int lda, long sAb, long sA2,
    const h16* __restrict__ Bh, int ldb, long sBb, long sB2,
    const float* __restrict__ bias, const float* __restrict__ res,
    float* __restrict__ C, h16* __restrict__ Ch,
    int ldc, long sCb, long sC2, int K, int Nreal, float alpha, int flags)
{
    constexpr int ASE = 128 * 72;           // BK=64, stride 72
    constexpr int BSE = BN_ * 72;           // TRB: 64 k-rows x 72 (BN_=64 only)
    constexpr int STE = ASE + BSE;
    constexpr int WN = BN_ / 2;
    constexpr int JB = WN / 8;
    extern __shared__ __align__(16) h16 sm[];

    int n0 = blockIdx.x * BN_;
    int m0 = blockIdx.y * 128;
    if ((flags & 4) && n0 >= m0 + 128) return;

    int z = blockIdx.z, zb = z / H_, zh = z % H_;
    Ah += (long)zb * sAb + (long)zh * sA2;
    Bh += (long)zb * sBb + (long)zh * sB2;
    long cOff = (long)zb * sCb + (long)zh * sC2;

    int tid = threadIdx.x, lane = tid & 31, wid = tid >> 5;
    int wm = wid & 1, wn = wid >> 1;
    int g = lane >> 2, tig = lane & 3;
    unsigned sbase = (unsigned)__cvta_generic_to_shared(sm);

    int Keff = (flags & 8) ? min(K, m0 + 128) : K;
    int nch = Keff >> 6;

    auto load_stage = [&](int st, int k0) {
        unsigned aH = sbase + (unsigned)st * STE * 2;
        unsigned bH = aH + ASE * 2;
#pragma unroll
        for (int i = 0; i < 8; i++) {
            int c = tid + i * 128, row = c >> 3, kg = c & 7;
            unsigned off = (unsigned)(row * 72 + kg * 8) * 2;
            CPA16(aH + off, Ah + (long)(m0 + row) * lda + k0 + kg * 8);
        }
        if (TRB) {   // B[K,N]: 64 k-rows x 64 cols
#pragma unroll
            for (int i = 0; i < 4; i++) {
                int c = tid + i * 128, krow = c >> 3, ng = c & 7;
                unsigned off = (unsigned)(krow * 72 + ng * 8) * 2;
                CPA16(bH + off, Bh + (long)(k0 + krow) * ldb + n0 + ng * 8);
            }
        } else {     // B[N,K]
#pragma unroll
            for (int i = 0; i < BN_ / 16; i++) {
                int c = tid + i * 128, row = c >> 3, kg = c & 7;
                unsigned off = (unsigned)(row * 72 + kg * 8) * 2;
                CPA16(bH + off, Bh + (long)(n0 + row) * ldb + k0 + kg * 8);
            }
        }
        asm volatile("cp.async.commit_group;");
    };

    float4 acc[4][JB];
#pragma unroll
    for (int i = 0; i < 4; i++)
#pragma unroll
        for (int j = 0; j < JB; j++) acc[i][j] = make_float4(0.f, 0.f, 0.f, 0.f);

    int a_r = (lane & 7) + ((lane >> 3) & 1) * 8;
    int a_c8 = (lane >> 4) * 8;
    int bt_n = ((lane >> 4) << 3) + (lane & 7);
    int bt_k8 = ((lane >> 3) & 1) * 8;
    int bn_kr = ((lane >> 3) & 1) * 8 + (lane & 7);
    int bn_n8 = (lane >> 4) * 8;

    load_stage(0, 0);
    for (int it = 0; it < nch; it++) {
        int st = it & 1;
        if (it + 1 < nch) {
            load_stage(st ^ 1, (it + 1) * 64);
            asm volatile("cp.async.wait_group 1;");
        } else {
            asm volatile("cp.async.wait_group 0;");
        }
        __syncthreads();
        unsigned aAh = sbase + (unsigned)st * STE * 2;
        unsigned aBh = aAh + ASE * 2;
#pragma unroll
        for (int ks = 0; ks < 4; ks++) {
            unsigned ah[4][4], bh[JB/2][4];
#pragma unroll
            for (int mi = 0; mi < 4; mi++) {
                unsigned off = (unsigned)(((wm * 64 + mi * 16 + a_r) * 72) + ks * 16 + a_c8) * 2;
                LDSM4(ah[mi], aAh + off);
            }
            if (TRB) {
#pragma unroll
                for (int jp = 0; jp < JB/2; jp++) {
                    unsigned off = (unsigned)(((ks * 16 + bn_kr) * 72) + wn * WN + jp * 16 + bn_n8) * 2;
                    LDSM4T(bh[jp], aBh + off);
                }
            } else {
#pragma unroll
                for (int jp = 0; jp < JB/2; jp++) {
                    unsigned off = (unsigned)(((wn * WN + jp * 16 + bt_n) * 72) + ks * 16 + bt_k8) * 2;
                    LDSM4(bh[jp], aBh + off);
                }
            }
#pragma unroll
            for (int mi = 0; mi < 4; mi++) {
#pragma unroll
                for (int j = 0; j < JB; j++) {
                    int jp = j >> 1, o = (j & 1) << 1;
                    MMA4(acc[mi][j], ah[mi], bh[jp][o], bh[jp][o + 1]);
                }
            }
        }
        __syncthreads();
    }

    float* Cp = C ? C + cOff : nullptr;
    h16* Chp = Ch ? Ch + cOff : nullptr;
#pragma unroll
    for (int mi = 0; mi < 4; mi++) {
#pragma unroll
        for (int j = 0; j < JB; j++) {
            int col = n0 + wn * WN + j * 8 + tig * 2;
            if (col >= Nreal) continue;
            int row0 = m0 + wm * 64 + mi * 16 + g, row1 = row0 + 8;
            float4 a = acc[mi][j];
            float2 bb = bias ? *(const float2*)(bias + col) : make_float2(0.f, 0.f);
            float2 v0, v1;
            v0.x = a.x * alpha + bb.x; v0.y = a.y * alpha + bb.y;
            v1.x = a.z * alpha + bb.x; v1.y = a.w * alpha + bb.y;
            if (res) {
                float2 q0 = *(const float2*)(res + (long)row0 * ldc + col);
                float2 q1 = *(const float2*)(res + (long)row1 * ldc + col);
                v0.x += q0.x; v0.y += q0.y; v1.x += q1.x; v1.y += q1.y;
            }
            if (flags & 2) {
                v0.x = fmaxf(v0.x, 0.f); v0.y = fmaxf(v0.y, 0.f);
                v1.x = fmaxf(v1.x, 0.f); v1.y = fmaxf(v1.y, 0.f);
            }
            if (Cp) {
                *(float2*)(Cp + (long)row0 * ldc + col) = v0;
                *(float2*)(Cp + (long)row1 * ldc + col) = v1;
            }
            if (Chp) {
                *(unsigned*)(Chp + (long)row0 * ldc + col) = pkh(v0.x, v0.y);
                *(unsigned*)(Chp + (long)row1 * ldc + col) = pkh(v1.x, v1.y);
            }
        }
    }
}

#define SMEM128 (2 * (128*72 + 128*72) * 2)
#define SMEM64  (2 * (128*72 + 64*72) * 2)

template<int BN_, int TRB>
static void runG(dim3 grid,
                 const h16* Ah, int lda, long sAb, long sA2,
                 const h16* Bh, int ldb, long sBb, long sB2,
                 const float* bias, const float* res,
                 float* C, h16* Ch, int ldc, long sCb, long sC2,
                 int K, int Nreal, float alpha, int flags)
{
    gemm_tc<BN_, TRB><<<grid, 128, BN_ == 128 ? SMEM128 : SMEM64>>>(
        Ah, lda, sAb, sA2, Bh, ldb, sBb, sB2,
        bias, res, C, Ch, ldc, sCb, sC2, K, Nreal, alpha, flags);
}

static void gemmW(const h16* Ah, int K, const h16* Bh, int N, int Nreal,
                  const float* bias, const float* res,
                  float* C, h16* Ch, int ldc, int relu)
{
    runG<128, 0>(dim3(N / 128, TOK / 128, 1), Ah, K, 0, 0, Bh, K, 0, 0,
                 bias, res, C, Ch, ldc, 0, 0, K, Nreal, 1.f, relu ? 2 : 0);
}

extern "C" void kernel_launch(void* const* d_in, const int* in_sizes, int n_in,
                              void* d_out, int out_size)
{
    (void)in_sizes; (void)n_in; (void)out_size;
    const int* src = (const int*)d_in[0];
    const int* target = (const int*)d_in[2];
    const float* src_emb = (const float*)d_in[4];
    const float* tgt_emb = (const float*)d_in[5];
    const float* pos_emb = (const float*)d_in[6];
    const float* eaw = (const float*)d_in[7];
    const float* eab = (const float*)d_in[8];
    const float* elg = (const float*)d_in[9];
    const float* elb = (const float*)d_in[10];
    const float* ef1 = (const float*)d_in[11];
    const float* eb1 = (const float*)d_in[12];
    const float* ef2 = (const float*)d_in[13];
    const float* eb2 = (const float*)d_in[14];
    const float* eng = (const float*)d_in[15];
    const float* enb = (const float*)d_in[16];
    const float* daw = (const float*)d_in[17];
    const float* dab = (const float*)d_in[18];
    const float* dlg = (const float*)d_in[19];
    const float* dlb = (const float*)d_in[20];
    const float* df1 = (const float*)d_in[21];
    const float* db1 = (const float*)d_in[22];
    const float* df2 = (const float*)d_in[23];
    const float* db2 = (const float*)d_in[24];
    const float* dng = (const float*)d_in[25];
    const float* dnb = (const float*)d_in[26];
    const float* ow = (const float*)d_in[27];
    const float* ob = (const float*)d_in[28];
    float* out = (float*)d_out;

    cudaFuncSetAttribute((const void*)gemm_tc<128,0>, cudaFuncAttributeMaxDynamicSharedMemorySize, SMEM128);
    cudaFuncSetAttribute((const void*)gemm_tc<64,1>, cudaFuncAttributeMaxDynamicSharedMemorySize, SMEM64);

    float* x;
    h16 *xn, *qkv, *cq, *o, *mem, *ffh, *ap;
    h16 *wea, *wda, *we1, *we2, *wd1, *wd2, *wo;
    cudaGetSymbolAddress((void**)&x, g_x);
    cudaGetSymbolAddress((void**)&xn, g_xn);
    cudaGetSymbolAddress((void**)&qkv, g_qkv);
    cudaGetSymbolAddress((void**)&cq, g_cq);
    cudaGetSymbolAddress((void**)&o, g_o);
    cudaGetSymbolAddress((void**)&mem, g_mem);
    cudaGetSymbolAddress((void**)&ffh, g_ffh);
    cudaGetSymbolAddress((void**)&ap, g_ap);
    cudaGetSymbolAddress((void**)&wea, g_wea);
    cudaGetSymbolAddress((void**)&wda, g_wda);
    cudaGetSymbolAddress((void**)&we1, g_we1);
    cudaGetSymbolAddress((void**)&we2, g_we2);
    cudaGetSymbolAddress((void**)&wd1, g_wd1);
    cudaGetSymbolAddress((void**)&wd2, g_wd2);
    cudaGetSymbolAddress((void**)&wo, g_wo);

    dim3 tb(32, 8);
    ttrans_kernel<<<dim3(24, 12, L_*4), tb>>>(eaw, wea, D_, D_, D_);
    ttrans_kernel<<<dim3(24, 12, L_*8), tb>>>(daw, wda, D_, D_, D_);
    ttrans_kernel<<<dim3(96, 12, L_), tb>>>(ef1, we1, D_, FF_, FF_);
    ttrans_kernel<<<dim3(24, 48, L_), tb>>>(ef2, we2, FF_, D_, D_);
    ttrans_kernel<<<dim3(96, 12, L_), tb>>>(df1, wd1, D_, FF_, FF_);
    ttrans_kernel<<<dim3(24, 48, L_), tb>>>(df2, wd2, FF_, D_, D_);
    ttrans_kernel<<<dim3(VP/32, 12, 1), tb>>>(ow, wo, D_, V_, VP);

    const long DD = (long)D_ * D_;
    const long SS = (long)S_ * S_;
    const int nblk = (TOK * D_ + 255) / 256;

    // attention: Q [*,ldq], K [*,ldk] K-major, V [s,ldv] direct (trans path)
    auto attention = [&](const h16* qH, int ldq, long sqb,
                         const h16* kH, int ldk, long skb,
                         const h16* vH, int ldv, long svb, int causal) {
        runG<128, 0>(dim3(8, 8, B_ * H_),
                     qH, ldq, sqb, 64, kH, ldk, skb, 64,
                     nullptr, nullptr, nullptr, ap,
                     S_, (long)H_ * SS, SS, 64, S_, 0.125f, causal ? 4 : 0);
        softmax_kernel<<<B_ * H_ * S_, 256>>>(ap, causal);
        runG<64, 1>(dim3(1, 8, B_ * H_),
                    ap, S_, (long)H_ * SS, SS,
                    vH, ldv, svb, 64,
                    nullptr, nullptr, nullptr, o,
                    D_, (long)S_ * D_, 64, S_, 64, 1.f, causal ? 8 : 0);
    };

    // ================= encoder =================
    embed_kernel<<<nblk, 256>>>(src, src_emb, pos_emb, x);
    for (int l = 0; l < L_; l++) {
        const h16* wh = wea + (long)l * 4 * DD;
        const float* bb = eab + (long)l * 4 * D_;
        ln_kernel<<<TOK, 256>>>(x, elg + (l*2)*D_, elb + (l*2)*D_, xn);
        gemmW(xn, D_, wh, QKV, QKV, bb, nullptr, nullptr, qkv, QKV, 0);
        attention(qkv, QKV, (long)S_ * QKV, qkv + 768, QKV, (long)S_ * QKV,
                  qkv + 1536, QKV, (long)S_ * QKV, 0);
        gemmW(o, D_, wh + 3*DD, D_, D_, bb + 3*D_, x, x, nullptr, D_, 0);
        ln_kernel<<<TOK, 256>>>(x, elg + (l*2+1)*D_, elb + (l*2+1)*D_, xn);
        gemmW(xn, D_, we1 + (long)l*FF_*D_, FF_, FF_, eb1 + l*FF_, nullptr, nullptr, ffh, FF_, 1);
        gemmW(ffh, FF_, we2 + (long)l*D_*FF_, D_, D_, eb2 + l*D_, x, x, nullptr, D_, 0);
    }
    ln_kernel<<<TOK, 256>>>(x, eng, enb, mem);

    // ================= decoder =================
    embed_kernel<<<nblk, 256>>>(target, tgt_emb, pos_emb, x);
    for (int l = 0; l < L_; l++) {
        const h16* wh = wda + (long)l * 8 * DD;
        const float* bb = dab + (long)l * 8 * D_;
        // causal self-attention (fused QKV)
        ln_kernel<<<TOK, 256>>>(x, dlg + (l*3)*D_, dlb + (l*3)*D_, xn);
        gemmW(xn, D_, wh, QKV, QKV, bb, nullptr, nullptr, qkv, QKV, 0);
        attention(qkv, QKV, (long)S_ * QKV, qkv + 768, QKV, (long)S_ * QKV,
                  qkv + 1536, QKV, (long)S_ * QKV, 1);
        gemmW(o, D_, wh + 3*DD, D_, D_, bb + 3*D_, x, x, nullptr, D_, 0);
        // cross-attention (fused KV from mem)
        ln_kernel<<<TOK, 256>>>(x, dlg + (l*3+1)*D_, dlb + (l*3+1)*D_, xn);
        gemmW(xn, D_, wh + 4*DD, D_, D_, bb + 4*D_, nullptr, nullptr, cq, D_, 0);
        gemmW(mem, D_, wh + 5*DD, 2*D_, 2*D_, bb + 5*D_, nullptr, nullptr, qkv, 2*D_, 0);
        attention(cq, D_, (long)S_ * D_, qkv, 2*D_, (long)S_ * 2 * D_,
                  qkv + 768, 2*D_, (long)S_ * 2 * D_, 0);
        gemmW(o, D_, wh + 7*DD, D_, D_, bb + 7*D_, x, x, nullptr, D_, 0);
        // FFN
        ln_kernel<<<TOK, 256>>>(x, dlg + (l*3+2)*D_, dlb + (l*3+2)*D_, xn);
        gemmW(xn, D_, wd1 + (long)l*FF_*D_, FF_, FF_, db1 + l*FF_, nullptr, nullptr, ffh, FF_, 1);
        gemmW(ffh, FF_, wd2 + (long)l*D_*FF_, D_, D_, db2 + l*D_, x, x, nullptr, D_, 0);
    }
    ln_kernel<<<TOK, 256>>>(x, dng, dnb, xn);

    // ================= output projection =================
    gemmW(xn, D_, wo, VP, V_, ob, nullptr, out, nullptr, V_, 0);
}

// round 14
// speedup vs baseline: 1.5137x; 1.3411x over previous
#include <cuda_runtime.h>
#include <cuda_fp16.h>
#include <cstdint>

#define B_ 4
#define S_ 1024
#define D_ 768
#define H_ 12
#define L_ 4
#define V_ 8000
#define VP 8064
#define FF_ 3072
#define TOK 4096
#define QKV 2304
#define EPSF 1e-5f
typedef __half h16;
typedef __half2 h162;

// ---------------- scratch ----------------
__device__ float g_x[TOK * D_];
__device__ h16 g_xn[TOK * D_];
__device__ h16 g_qkv[TOK * QKV];
__device__ h16 g_cq[TOK * D_];
__device__ h16 g_o[TOK * D_];
__device__ h16 g_mem[TOK * D_];
__device__ h16 g_ffh[TOK * FF_];
__device__ h16 g_wea[L_*4*D_*D_];
__device__ h16 g_wda[L_*8*D_*D_];
__device__ h16 g_we1[L_*FF_*D_];
__device__ h16 g_we2[L_*D_*FF_];
__device__ h16 g_wd1[L_*FF_*D_];
__device__ h16 g_wd2[L_*D_*FF_];
__device__ h16 g_wo[(long)VP * D_];

// ---------------- transpose+convert weights ----------------
__global__ void ttrans_kernel(const float* __restrict__ W, h16* __restrict__ Wh,
                              int K, int N, int Npad)
{
    __shared__ float t[64][33];
    int z = blockIdx.z;
    W += (long)z * K * N; Wh += (long)z * Npad * K;
    int n0 = blockIdx.x * 32, k0 = blockIdx.y * 64;
    int tx = threadIdx.x, ty = threadIdx.y;
#pragma unroll
    for (int j = 0; j < 8; j++) {
        int k = k0 + ty + 8 * j, n = n0 + tx;
        t[ty + 8 * j][tx] = (n < N) ? W[(long)k * N + n] : 0.f;
    }
    __syncthreads();
#pragma unroll
    for (int j = 0; j < 4; j++) {
        int n = n0 + ty + 8 * j;
        h162 v;
        v.x = __float2half_rn(t[2 * tx][ty + 8 * j]);
        v.y = __float2half_rn(t[2 * tx + 1][ty + 8 * j]);
        *(h162*)(Wh + (long)n * K + k0 + 2 * tx) = v;
    }
}

// ---------------- embed ----------------
__global__ void embed_kernel(const int* __restrict__ tok, const float* __restrict__ emb,
                             const float* __restrict__ pos, float* __restrict__ out)
{
    int i = blockIdx.x * blockDim.x + threadIdx.x;
    if (i >= TOK * D_) return;
    int d = i % D_, t = i / D_, s = t % S_;
    out[i] = emb[(long)tok[t] * D_ + d] + pos[(long)s * D_ + d];
}

// ---------------- layernorm -> fp16 (warp-shuffle reduction) ----------------
__global__ void __launch_bounds__(256) ln_kernel(const float* __restrict__ x,
    const float* __restrict__ g, const float* __restrict__ b, h16* __restrict__ oh)
{
    int row = blockIdx.x, tid = threadIdx.x;
    int lane = tid & 31, wid = tid >> 5;
    const float* xr = x + (long)row * D_;
    float v[3], lsum = 0.f, lsq = 0.f;
#pragma unroll
    for (int i = 0; i < 3; i++) {
        float t = xr[tid + i * 256];
        v[i] = t; lsum += t; lsq += t * t;
    }
#pragma unroll
    for (int off = 16; off > 0; off >>= 1) {
        lsum += __shfl_xor_sync(0xffffffffu, lsum, off);
        lsq  += __shfl_xor_sync(0xffffffffu, lsq, off);
    }
    __shared__ float w1[8], w2[8];
    if (lane == 0) { w1[wid] = lsum; w2[wid] = lsq; }
    __syncthreads();
    float ts = 0.f, tq = 0.f;
#pragma unroll
    for (int i = 0; i < 8; i++) { ts += w1[i]; tq += w2[i]; }
    float mean = ts * (1.f / D_);
    float inv = rsqrtf(tq * (1.f / D_) - mean * mean + EPSF);
#pragma unroll
    for (int i = 0; i < 3; i++) {
        int d = tid + i * 256;
        oh[(long)row * D_ + d] = __float2half_rn((v[i] - mean) * inv * g[d] + b[d]);
    }
}

// ---------------- asm helpers ----------------
#define CPA16(dst, src) \
    asm volatile("cp.async.cg.shared.global [%0], [%1], 16;" :: "r"(dst), "l"(src))
#define LDSM4(r, addr) \
    asm volatile("ldmatrix.sync.aligned.m8n8.x4.shared.b16 {%0,%1,%2,%3}, [%4];" \
                 : "=r"((r)[0]), "=r"((r)[1]), "=r"((r)[2]), "=r"((r)[3]) : "r"(addr))
#define LDSM4T(r, addr) \
    asm volatile("ldmatrix.sync.aligned.m8n8.x4.trans.shared.b16 {%0,%1,%2,%3}, [%4];" \
                 : "=r"((r)[0]), "=r"((r)[1]), "=r"((r)[2]), "=r"((r)[3]) : "r"(addr))
#define MMA4(c, a, b0, b1)                                                    \
    asm volatile("mma.sync.aligned.m16n8k16.row.col.f32.f16.f16.f32 "         \
                 "{%0,%1,%2,%3}, {%4,%5,%6,%7}, {%8,%9}, {%0,%1,%2,%3};"      \
                 : "+f"((c).x), "+f"((c).y), "+f"((c).z), "+f"((c).w)         \
                 : "r"((a)[0]), "r"((a)[1]), "r"((a)[2]), "r"((a)[3]),        \
                   "r"(b0), "r"(b1))

__device__ __forceinline__ unsigned pkh(float x, float y)
{
    h162 hb;
    hb.x = __float2half_rn(x); hb.y = __float2half_rn(y);
    return *reinterpret_cast<unsigned*>(&hb);
}

// =====================================================================
// flash attention (1-term fp16): Q tile 64x64, KV streamed 64-row tiles.
// fp32 scores + online softmax in registers; P,V fp16; O fp16 out.
// =====================================================================
#define SMEMF ((64*72 + 2*2*64*72) * 2)     // Q + 2 stages x (K,V) = 46080 B

__global__ void __launch_bounds__(128, 2) flash_kernel(
    const h16* __restrict__ Qh, int ldq,
    const h16* __restrict__ Kh, int ldk,
    const h16* __restrict__ Vh, int ldv,
    h16* __restrict__ Oh, int causal)
{
    extern __shared__ __align__(16) h16 sm[];
    int qt = blockIdx.x, z = blockIdx.y, zb = z / H_, zh = z % H_;
    int tid = threadIdx.x, lane = tid & 31, wid = tid >> 5;
    int g = lane >> 2, tig = lane & 3;
    unsigned sbase = (unsigned)__cvta_generic_to_shared(sm);

    const h16* qP = Qh + (long)zb * S_ * ldq + zh * 64;
    const h16* kP = Kh + (long)zb * S_ * ldk + zh * 64;
    const h16* vP = Vh + (long)zb * S_ * ldv + zh * 64;

    const unsigned QOFF = 0;
    const unsigned ST0 = 64 * 72 * 2;
    const unsigned STSZ = 2 * 64 * 72 * 2;     // K + V per stage

    // load Q
#pragma unroll
    for (int i = 0; i < 4; i++) {
        int c = tid + i * 128, row = c >> 3, seg = c & 7;
        unsigned off = (unsigned)(row * 72 + seg * 8) * 2;
        CPA16(sbase + QOFF + off, qP + (long)(qt * 64 + row) * ldq + seg * 8);
    }
    asm volatile("cp.async.commit_group;");

    auto loadKV = [&](int st, int kt) {
        unsigned b = sbase + ST0 + st * STSZ;
#pragma unroll
        for (int i = 0; i < 4; i++) {
            int c = tid + i * 128, row = c >> 3, seg = c & 7;
            unsigned off = (unsigned)(row * 72 + seg * 8) * 2;
            long go = (long)(kt * 64 + row);
            CPA16(b + off,             kP + go * ldk + seg * 8);
            CPA16(b + 64*72*2 + off,   vP + go * ldv + seg * 8);
        }
        asm volatile("cp.async.commit_group;");
    };

    int nkt = causal ? (qt + 1) : (S_ / 64);
    loadKV(0, 0);

    asm volatile("cp.async.wait_group 0;");
    __syncthreads();
    int a_r = (lane & 7) + ((lane >> 3) & 1) * 8;
    int a_c8 = (lane >> 4) * 8;
    int bt_n = ((lane >> 4) << 3) + (lane & 7);
    int bt_k8 = ((lane >> 3) & 1) * 8;
    int bn_kr = ((lane >> 3) & 1) * 8 + (lane & 7);
    int bn_n8 = (lane >> 4) * 8;

    unsigned qa[4][4];
#pragma unroll
    for (int ks = 0; ks < 4; ks++) {
        unsigned off = (unsigned)(((wid * 16 + a_r) * 72) + ks * 16 + a_c8) * 2;
        LDSM4(qa[ks], sbase + QOFF + off);
    }

    float m0 = -1e30f, m1 = -1e30f, l0 = 0.f, l1 = 0.f;
    float4 oacc[8];
#pragma unroll
    for (int j = 0; j < 8; j++) oacc[j] = make_float4(0.f, 0.f, 0.f, 0.f);

    for (int kt = 0; kt < nkt; kt++) {
        int st = kt & 1;
        if (kt + 1 < nkt) {
            loadKV(st ^ 1, kt + 1);
            asm volatile("cp.async.wait_group 1;");
        } else {
            asm volatile("cp.async.wait_group 0;");
        }
        __syncthreads();
        unsigned kb = sbase + ST0 + st * STSZ;
        unsigned vb = kb + 64 * 72 * 2;

        // ---- S = Q K^T ----
        float4 sacc[8];
#pragma unroll
        for (int j = 0; j < 8; j++) sacc[j] = make_float4(0.f, 0.f, 0.f, 0.f);
#pragma unroll
        for (int ks = 0; ks < 4; ks++) {
            unsigned kh[4][4];
#pragma unroll
            for (int jp = 0; jp < 4; jp++) {
                unsigned off = (unsigned)(((jp * 16 + bt_n) * 72) + ks * 16 + bt_k8) * 2;
                LDSM4(kh[jp], kb + off);
            }
#pragma unroll
            for (int j = 0; j < 8; j++) {
                int jp = j >> 1, o = (j & 1) << 1;
                MMA4(sacc[j], qa[ks], kh[jp][o], kh[jp][o + 1]);
            }
        }
        // ---- scale + mask + online softmax ----
        int row0 = qt * 64 + wid * 16 + g, row1 = row0 + 8;
        float rx0 = -1e30f, rx1 = -1e30f;
#pragma unroll
        for (int j = 0; j < 8; j++) {
            float4 s = sacc[j];
            s.x *= 0.125f; s.y *= 0.125f; s.z *= 0.125f; s.w *= 0.125f;
            if (causal && kt == qt) {
                int c0 = kt * 64 + j * 8 + 2 * tig, c1 = c0 + 1;
                if (c0 > row0) s.x = -1e30f;
                if (c1 > row0) s.y = -1e30f;
                if (c0 > row1) s.z = -1e30f;
                if (c1 > row1) s.w = -1e30f;
            }
            rx0 = fmaxf(rx0, fmaxf(s.x, s.y));
            rx1 = fmaxf(rx1, fmaxf(s.z, s.w));
            sacc[j] = s;
        }
        rx0 = fmaxf(rx0, __shfl_xor_sync(0xffffffffu, rx0, 1));
        rx0 = fmaxf(rx0, __shfl_xor_sync(0xffffffffu, rx0, 2));
        rx1 = fmaxf(rx1, __shfl_xor_sync(0xffffffffu, rx1, 1));
        rx1 = fmaxf(rx1, __shfl_xor_sync(0xffffffffu, rx1, 2));
        float m0n = fmaxf(m0, rx0), m1n = fmaxf(m1, rx1);
        float sc0 = __expf(m0 - m0n), sc1 = __expf(m1 - m1n);
        m0 = m0n; m1 = m1n;
        float rs0 = 0.f, rs1 = 0.f;
#pragma unroll
        for (int j = 0; j < 8; j++) {
            float4 s = sacc[j];
            s.x = __expf(s.x - m0n); s.y = __expf(s.y - m0n);
            s.z = __expf(s.z - m1n); s.w = __expf(s.w - m1n);
            rs0 += s.x + s.y; rs1 += s.z + s.w;
            sacc[j] = s;
        }
        rs0 += __shfl_xor_sync(0xffffffffu, rs0, 1);
        rs0 += __shfl_xor_sync(0xffffffffu, rs0, 2);
        rs1 += __shfl_xor_sync(0xffffffffu, rs1, 1);
        rs1 += __shfl_xor_sync(0xffffffffu, rs1, 2);
        l0 = l0 * sc0 + rs0; l1 = l1 * sc1 + rs1;
#pragma unroll
        for (int j = 0; j < 8; j++) {
            oacc[j].x *= sc0; oacc[j].y *= sc0;
            oacc[j].z *= sc1; oacc[j].w *= sc1;
        }
        // ---- pack P to fp16 a-fragments ----
        unsigned pa[4][4];
#pragma unroll
        for (int c = 0; c < 4; c++) {
            float4 b0 = sacc[2 * c], b1 = sacc[2 * c + 1];
            pa[c][0] = pkh(b0.x, b0.y);
            pa[c][1] = pkh(b0.z, b0.w);
            pa[c][2] = pkh(b1.x, b1.y);
            pa[c][3] = pkh(b1.z, b1.w);
        }
        // ---- O += P V ----
#pragma unroll
        for (int ks = 0; ks < 4; ks++) {
            unsigned vh[4][4];
#pragma unroll
            for (int jp = 0; jp < 4; jp++) {
                unsigned off = (unsigned)(((ks * 16 + bn_kr) * 72) + jp * 16 + bn_n8) * 2;
                LDSM4T(vh[jp], vb + off);
            }
#pragma unroll
            for (int j = 0; j < 8; j++) {
                int jp = j >> 1, o = (j & 1) << 1;
                MMA4(oacc[j], pa[ks], vh[jp][o], vh[jp][o + 1]);
            }
        }
        __syncthreads();
    }

    // ---- normalize + write ----
    float i0 = 1.f / l0, i1 = 1.f / l1;
    long r0 = (long)(zb * S_ + qt * 64 + wid * 16 + g) * D_ + zh * 64;
    long r1 = r0 + 8 * D_;
#pragma unroll
    for (int j = 0; j < 8; j++) {
        int col = j * 8 + 2 * tig;
        *(unsigned*)(Oh + r0 + col) = pkh(oacc[j].x * i0, oacc[j].y * i0);
        *(unsigned*)(Oh + r1 + col) = pkh(oacc[j].z * i1, oacc[j].w * i1);
    }
}

// =====================================================================
// linear GEMM — R13 kernel (2-stage, BK=64), B [N,K] K-major only.
// =====================================================================
__global__ void __launch_bounds__(128, 2) gemm_tc(
    const h16* __restrict__ Ah, int lda,
    const h16* __restrict__ Bh, int ldb,
    const float* __restrict__ bias, const float* __restrict__ res,
    float* __restrict__ C, h16* __restrict__ Ch,
    int ldc, int K, int Nreal, int flags)
{
    constexpr int ASE = 128 * 72;
    constexpr int BSE = 128 * 72;
    constexpr int STE = ASE + BSE;
    extern __shared__ __align__(16) h16 sm[];

    int n0 = blockIdx.x * 128;
    int m0 = blockIdx.y * 128;

    int tid = threadIdx.x, lane = tid & 31, wid = tid >> 5;
    int wm = wid & 1, wn = wid >> 1;
    int g = lane >> 2, tig = lane & 3;
    unsigned sbase = (unsigned)__cvta_generic_to_shared(sm);
    int nch = K >> 6;

    auto load_stage = [&](int st, int k0) {
        unsigned aH = sbase + (unsigned)st * STE * 2;
        unsigned bH = aH + ASE * 2;
#pragma unroll
        for (int i = 0; i < 8; i++) {
            int c = tid + i * 128, row = c >> 3, kg = c & 7;
            unsigned off = (unsigned)(row * 72 + kg * 8) * 2;
            CPA16(aH + off, Ah + (long)(m0 + row) * lda + k0 + kg * 8);
        }
#pragma unroll
        for (int i = 0; i < 8; i++) {
            int c = tid + i * 128, row = c >> 3, kg = c & 7;
            unsigned off = (unsigned)(row * 72 + kg * 8) * 2;
            CPA16(bH + off, Bh + (long)(n0 + row) * ldb + k0 + kg * 8);
        }
        asm volatile("cp.async.commit_group;");
    };

    float4 acc[4][8];
#pragma unroll
    for (int i = 0; i < 4; i++)
#pragma unroll
        for (int j = 0; j < 8; j++) acc[i][j] = make_float4(0.f, 0.f, 0.f, 0.f);

    int a_r = (lane & 7) + ((lane >> 3) & 1) * 8;
    int a_c8 = (lane >> 4) * 8;
    int bt_n = ((lane >> 4) << 3) + (lane & 7);
    int bt_k8 = ((lane >> 3) & 1) * 8;

    load_stage(0, 0);
    for (int it = 0; it < nch; it++) {
        int st = it & 1;
        if (it + 1 < nch) {
            load_stage(st ^ 1, (it + 1) * 64);
            asm volatile("cp.async.wait_group 1;");
        } else {
            asm volatile("cp.async.wait_group 0;");
        }
        __syncthreads();
        unsigned aAh = sbase + (unsigned)st * STE * 2;
        unsigned aBh = aAh + ASE * 2;
#pragma unroll
        for (int ks = 0; ks < 4; ks++) {
            unsigned ah[4][4], bh[4][4];
#pragma unroll
            for (int mi = 0; mi < 4; mi++) {
                unsigned off = (unsigned)(((wm * 64 + mi * 16 + a_r) * 72) + ks * 16 + a_c8) * 2;
                LDSM4(ah[mi], aAh + off);
            }
#pragma unroll
            for (int jp = 0; jp < 4; jp++) {
                unsigned off = (unsigned)(((wn * 64 + jp * 16 + bt_n) * 72) + ks * 16 + bt_k8) * 2;
                LDSM4(bh[jp], aBh + off);
            }
#pragma unroll
            for (int mi = 0; mi < 4; mi++) {
#pragma unroll
                for (int j = 0; j < 8; j++) {
                    int jp = j >> 1, o = (j & 1) << 1;
                    MMA4(acc[mi][j], ah[mi], bh[jp][o], bh[jp][o + 1]);
                }
            }
        }
        __syncthreads();
    }

#pragma unroll
    for (int mi = 0; mi < 4; mi++) {
#pragma unroll
        for (int j = 0; j < 8; j++) {
            int col = n0 + wn * 64 + j * 8 + tig * 2;
            if (col >= Nreal) continue;
            int row0 = m0 + wm * 64 + mi * 16 + g, row1 = row0 + 8;
            float4 a = acc[mi][j];
            float2 bb = bias ? *(const float2*)(bias + col) : make_float2(0.f, 0.f);
            float2 v0, v1;
            v0.x = a.x + bb.x; v0.y = a.y + bb.y;
            v1.x = a.z + bb.x; v1.y = a.w + bb.y;
            if (res) {
                float2 q0 = *(const float2*)(res + (long)row0 * ldc + col);
                float2 q1 = *(const float2*)(res + (long)row1 * ldc + col);
                v0.x += q0.x; v0.y += q0.y; v1.x += q1.x; v1.y += q1.y;
            }
            if (flags & 2) {
                v0.x = fmaxf(v0.x, 0.f); v0.y = fmaxf(v0.y, 0.f);
                v1.x = fmaxf(v1.x, 0.f); v1.y = fmaxf(v1.y, 0.f);
            }
            if (C) {
                *(float2*)(C + (long)row0 * ldc + col) = v0;
                *(float2*)(C + (long)row1 * ldc + col) = v1;
            }
            if (Ch) {
                *(unsigned*)(Ch + (long)row0 * ldc + col) = pkh(v0.x, v0.y);
                *(unsigned*)(Ch + (long)row1 * ldc + col) = pkh(v1.x, v1.y);
            }
        }
    }
}

#define SMEMG (2 * (128*72 + 128*72) * 2)

static void gemmW(const h16* Ah, int K, const h16* Bh, int N, int Nreal,
                  const float* bias, const float* res,
                  float* C, h16* Ch, int ldc, int relu)
{
    gemm_tc<<<dim3(N / 128, TOK / 128, 1), 128, SMEMG>>>(
        Ah, K, Bh, K, bias, res, C, Ch, ldc, K, Nreal, relu ? 2 : 0);
}

extern "C" void kernel_launch(void* const* d_in, const int* in_sizes, int n_in,
                              void* d_out, int out_size)
{
    (void)in_sizes; (void)n_in; (void)out_size;
    const int* src = (const int*)d_in[0];
    const int* target = (const int*)d_in[2];
    const float* src_emb = (const float*)d_in[4];
    const float* tgt_emb = (const float*)d_in[5];
    const float* pos_emb = (const float*)d_in[6];
    const float* eaw = (const float*)d_in[7];
    const float* eab = (const float*)d_in[8];
    const float* elg = (const float*)d_in[9];
    const float* elb = (const float*)d_in[10];
    const float* ef1 = (const float*)d_in[11];
    const float* eb1 = (const float*)d_in[12];
    const float* ef2 = (const float*)d_in[13];
    const float* eb2 = (const float*)d_in[14];
    const float* eng = (const float*)d_in[15];
    const float* enb = (const float*)d_in[16];
    const float* daw = (const float*)d_in[17];
    const float* dab = (const float*)d_in[18];
    const float* dlg = (const float*)d_in[19];
    const float* dlb = (const float*)d_in[20];
    const float* df1 = (const float*)d_in[21];
    const float* db1 = (const float*)d_in[22];
    const float* df2 = (const float*)d_in[23];
    const float* db2 = (const float*)d_in[24];
    const float* dng = (const float*)d_in[25];
    const float* dnb = (const float*)d_in[26];
    const float* ow = (const float*)d_in[27];
    const float* ob = (const float*)d_in[28];
    float* out = (float*)d_out;

    cudaFuncSetAttribute(gemm_tc, cudaFuncAttributeMaxDynamicSharedMemorySize, SMEMG);
    cudaFuncSetAttribute(flash_kernel, cudaFuncAttributeMaxDynamicSharedMemorySize, SMEMF);

    float* x;
    h16 *xn, *qkv, *cq, *o, *mem, *ffh;
    h16 *wea, *wda, *we1, *we2, *wd1, *wd2, *wo;
    cudaGetSymbolAddress((void**)&x, g_x);
    cudaGetSymbolAddress((void**)&xn, g_xn);
    cudaGetSymbolAddress((void**)&qkv, g_qkv);
    cudaGetSymbolAddress((void**)&cq, g_cq);
    cudaGetSymbolAddress((void**)&o, g_o);
    cudaGetSymbolAddress((void**)&mem, g_mem);
    cudaGetSymbolAddress((void**)&ffh, g_ffh);
    cudaGetSymbolAddress((void**)&wea, g_wea);
    cudaGetSymbolAddress((void**)&wda, g_wda);
    cudaGetSymbolAddress((void**)&we1, g_we1);
    cudaGetSymbolAddress((void**)&we2, g_we2);
    cudaGetSymbolAddress((void**)&wd1, g_wd1);
    cudaGetSymbolAddress((void**)&wd2, g_wd2);
    cudaGetSymbolAddress((void**)&wo, g_wo);

    dim3 tb(32, 8);
    ttrans_kernel<<<dim3(24, 12, L_*4), tb>>>(eaw, wea, D_, D_, D_);
    ttrans_kernel<<<dim3(24, 12, L_*8), tb>>>(daw, wda, D_, D_, D_);
    ttrans_kernel<<<dim3(96, 12, L_), tb>>>(ef1, we1, D_, FF_, FF_);
    ttrans_kernel<<<dim3(24, 48, L_), tb>>>(ef2, we2, FF_, D_, D_);
    ttrans_kernel<<<dim3(96, 12, L_), tb>>>(df1, wd1, D_, FF_, FF_);
    ttrans_kernel<<<dim3(24, 48, L_), tb>>>(df2, wd2, FF_, D_, D_);
    ttrans_kernel<<<dim3(VP/32, 12, 1), tb>>>(ow, wo, D_, V_, VP);

    const long DD = (long)D_ * D_;
    const int nblk = (TOK * D_ + 255) / 256;
    dim3 fg(16, B_ * H_);

    // ================= encoder =================
    embed_kernel<<<nblk, 256>>>(src, src_emb, pos_emb, x);
    for (int l = 0; l < L_; l++) {
        const h16* wh = wea + (long)l * 4 * DD;
        const float* bb = eab + (long)l * 4 * D_;
        ln_kernel<<<TOK, 256>>>(x, elg + (l*2)*D_, elb + (l*2)*D_, xn);
        gemmW(xn, D_, wh, QKV, QKV, bb, nullptr, nullptr, qkv, QKV, 0);
        flash_kernel<<<fg, 128, SMEMF>>>(qkv, QKV, qkv + 768, QKV, qkv + 1536, QKV, o, 0);
        gemmW(o, D_, wh + 3*DD, D_, D_, bb + 3*D_, x, x, nullptr, D_, 0);
        ln_kernel<<<TOK, 256>>>(x, elg + (l*2+1)*D_, elb + (l*2+1)*D_, xn);
        gemmW(xn, D_, we1 + (long)l*FF_*D_, FF_, FF_, eb1 + l*FF_, nullptr, nullptr, ffh, FF_, 1);
        gemmW(ffh, FF_, we2 + (long)l*D_*FF_, D_, D_, eb2 + l*D_, x, x, nullptr, D_, 0);
    }
    ln_kernel<<<TOK, 256>>>(x, eng, enb, mem);

    // ================= decoder =================
    embed_kernel<<<nblk, 256>>>(target, tgt_emb, pos_emb, x);
    for (int l = 0; l < L_; l++) {
        const h16* wh = wda + (long)l * 8 * DD;
        const float* bb = dab + (long)l * 8 * D_;
        // causal self-attention
        ln_kernel<<<TOK, 256>>>(x, dlg + (l*3)*D_, dlb + (l*3)*D_, xn);
        gemmW(xn, D_, wh, QKV, QKV, bb, nullptr, nullptr, qkv, QKV, 0);
        flash_kernel<<<fg, 128, SMEMF>>>(qkv, QKV, qkv + 768, QKV, qkv + 1536, QKV, o, 1);
        gemmW(o, D_, wh + 3*DD, D_, D_, bb + 3*D_, x, x, nullptr, D_, 0);
        // cross-attention
        ln_kernel<<<TOK, 256>>>(x, dlg + (l*3+1)*D_, dlb + (l*3+1)*D_, xn);
        gemmW(xn, D_, wh + 4*DD, D_, D_, bb + 4*D_, nullptr, nullptr, cq, D_, 0);
        gemmW(mem, D_, wh + 5*DD, 2*D_, 2*D_, bb + 5*D_, nullptr, nullptr, qkv, 2*D_, 0);
        flash_kernel<<<fg, 128, SMEMF>>>(cq, D_, qkv, 2*D_, qkv + 768, 2*D_, o, 0);
        gemmW(o, D_, wh + 7*DD, D_, D_, bb + 7*D_, x, x, nullptr, D_, 0);
        // FFN
        ln_kernel<<<TOK, 256>>>(x, dlg + (l*3+2)*D_, dlb + (l*3+2)*D_, xn);
        gemmW(xn, D_, wd1 + (long)l*FF_*D_, FF_, FF_, db1 + l*FF_, nullptr, nullptr, ffh, FF_, 1);
        gemmW(ffh, FF_, wd2 + (long)l*D_*FF_, D_, D_, db2 + l*D_, x, x, nullptr, D_, 0);
    }
    ln_kernel<<<TOK, 256>>>(x, dng, dnb, xn);

    // ================= output projection =================
    gemmW(xn, D_, wo, VP, V_, ob, nullptr, out, nullptr, V_, 0);
}

// round 15
// speedup vs baseline: 1.5727x; 1.0390x over previous
#include <cuda_runtime.h>
#include <cuda_fp16.h>
#include <cstdint>

#define B_ 4
#define S_ 1024
#define D_ 768
#define H_ 12
#define L_ 4
#define V_ 8000
#define VP 8064
#define FF_ 3072
#define TOK 4096
#define QKV 2304
#define EPSF 1e-5f
typedef __half h16;
typedef __half2 h162;

// ---------------- scratch ----------------
__device__ float g_x[TOK * D_];
__device__ h16 g_xn[TOK * D_];
__device__ h16 g_qkv[TOK * QKV];
__device__ h16 g_cq[TOK * D_];
__device__ h16 g_o[TOK * D_];
__device__ h16 g_mem[TOK * D_];
__device__ h16 g_ffh[TOK * FF_];
__device__ h16 g_wea[L_*4*D_*D_];
__device__ h16 g_wda[L_*8*D_*D_];
__device__ h16 g_we1[L_*FF_*D_];
__device__ h16 g_we2[L_*D_*FF_];
__device__ h16 g_wd1[L_*FF_*D_];
__device__ h16 g_wd2[L_*D_*FF_];
__device__ h16 g_wo[(long)VP * D_];

// ---------------- transpose+convert weights ----------------
__global__ void ttrans_kernel(const float* __restrict__ W, h16* __restrict__ Wh,
                              int K, int N, int Npad)
{
    __shared__ float t[64][33];
    int z = blockIdx.z;
    W += (long)z * K * N; Wh += (long)z * Npad * K;
    int n0 = blockIdx.x * 32, k0 = blockIdx.y * 64;
    int tx = threadIdx.x, ty = threadIdx.y;
#pragma unroll
    for (int j = 0; j < 8; j++) {
        int k = k0 + ty + 8 * j, n = n0 + tx;
        t[ty + 8 * j][tx] = (n < N) ? W[(long)k * N + n] : 0.f;
    }
    __syncthreads();
#pragma unroll
    for (int j = 0; j < 4; j++) {
        int n = n0 + ty + 8 * j;
        h162 v;
        v.x = __float2half_rn(t[2 * tx][ty + 8 * j]);
        v.y = __float2half_rn(t[2 * tx + 1][ty + 8 * j]);
        *(h162*)(Wh + (long)n * K + k0 + 2 * tx) = v;
    }
}

// ---------------- embed ----------------
__global__ void embed_kernel(const int* __restrict__ tok, const float* __restrict__ emb,
                             const float* __restrict__ pos, float* __restrict__ out)
{
    int i = blockIdx.x * blockDim.x + threadIdx.x;
    if (i >= TOK * D_) return;
    int d = i % D_, t = i / D_, s = t % S_;
    out[i] = emb[(long)tok[t] * D_ + d] + pos[(long)s * D_ + d];
}

// ---------------- layernorm -> fp16 (warp-shuffle reduction) ----------------
__global__ void __launch_bounds__(256) ln_kernel(const float* __restrict__ x,
    const float* __restrict__ g, const float* __restrict__ b, h16* __restrict__ oh)
{
    int row = blockIdx.x, tid = threadIdx.x;
    int lane = tid & 31, wid = tid >> 5;
    const float* xr = x + (long)row * D_;
    float v[3], lsum = 0.f, lsq = 0.f;
#pragma unroll
    for (int i = 0; i < 3; i++) {
        float t = xr[tid + i * 256];
        v[i] = t; lsum += t; lsq += t * t;
    }
#pragma unroll
    for (int off = 16; off > 0; off >>= 1) {
        lsum += __shfl_xor_sync(0xffffffffu, lsum, off);
        lsq  += __shfl_xor_sync(0xffffffffu, lsq, off);
    }
    __shared__ float w1[8], w2[8];
    if (lane == 0) { w1[wid] = lsum; w2[wid] = lsq; }
    __syncthreads();
    float ts = 0.f, tq = 0.f;
#pragma unroll
    for (int i = 0; i < 8; i++) { ts += w1[i]; tq += w2[i]; }
    float mean = ts * (1.f / D_);
    float inv = rsqrtf(tq * (1.f / D_) - mean * mean + EPSF);
#pragma unroll
    for (int i = 0; i < 3; i++) {
        int d = tid + i * 256;
        oh[(long)row * D_ + d] = __float2half_rn((v[i] - mean) * inv * g[d] + b[d]);
    }
}

// ---------------- asm helpers ----------------
#define CPA16(dst, src) \
    asm volatile("cp.async.cg.shared.global [%0], [%1], 16;" :: "r"(dst), "l"(src))
#define LDSM4(r, addr) \
    asm volatile("ldmatrix.sync.aligned.m8n8.x4.shared.b16 {%0,%1,%2,%3}, [%4];" \
                 : "=r"((r)[0]), "=r"((r)[1]), "=r"((r)[2]), "=r"((r)[3]) : "r"(addr))
#define LDSM4T(r, addr) \
    asm volatile("ldmatrix.sync.aligned.m8n8.x4.trans.shared.b16 {%0,%1,%2,%3}, [%4];" \
                 : "=r"((r)[0]), "=r"((r)[1]), "=r"((r)[2]), "=r"((r)[3]) : "r"(addr))
#define MMA4(c, a, b0, b1)                                                    \
    asm volatile("mma.sync.aligned.m16n8k16.row.col.f32.f16.f16.f32 "         \
                 "{%0,%1,%2,%3}, {%4,%5,%6,%7}, {%8,%9}, {%0,%1,%2,%3};"      \
                 : "+f"((c).x), "+f"((c).y), "+f"((c).z), "+f"((c).w)         \
                 : "r"((a)[0]), "r"((a)[1]), "r"((a)[2]), "r"((a)[3]),        \
                   "r"(b0), "r"(b1))

__device__ __forceinline__ unsigned pkh(float x, float y)
{
    h162 hb;
    hb.x = __float2half_rn(x); hb.y = __float2half_rn(y);
    return *reinterpret_cast<unsigned*>(&hb);
}

// =====================================================================
// flash attention (1-term fp16): Q tile 64x64, KV streamed 64-row tiles.
// =====================================================================
#define SMEMF ((64*72 + 2*2*64*72) * 2)

__global__ void __launch_bounds__(128, 2) flash_kernel(
    const h16* __restrict__ Qh, int ldq,
    const h16* __restrict__ Kh, int ldk,
    const h16* __restrict__ Vh, int ldv,
    h16* __restrict__ Oh, int causal)
{
    extern __shared__ __align__(16) h16 sm[];
    int qt = blockIdx.x, z = blockIdx.y, zb = z / H_, zh = z % H_;
    int tid = threadIdx.x, lane = tid & 31, wid = tid >> 5;
    int g = lane >> 2, tig = lane & 3;
    unsigned sbase = (unsigned)__cvta_generic_to_shared(sm);

    const h16* qP = Qh + (long)zb * S_ * ldq + zh * 64;
    const h16* kP = Kh + (long)zb * S_ * ldk + zh * 64;
    const h16* vP = Vh + (long)zb * S_ * ldv + zh * 64;

    const unsigned QOFF = 0;
    const unsigned ST0 = 64 * 72 * 2;
    const unsigned STSZ = 2 * 64 * 72 * 2;

#pragma unroll
    for (int i = 0; i < 4; i++) {
        int c = tid + i * 128, row = c >> 3, seg = c & 7;
        unsigned off = (unsigned)(row * 72 + seg * 8) * 2;
        CPA16(sbase + QOFF + off, qP + (long)(qt * 64 + row) * ldq + seg * 8);
    }
    asm volatile("cp.async.commit_group;");

    auto loadKV = [&](int st, int kt) {
        unsigned b = sbase + ST0 + st * STSZ;
#pragma unroll
        for (int i = 0; i < 4; i++) {
            int c = tid + i * 128, row = c >> 3, seg = c & 7;
            unsigned off = (unsigned)(row * 72 + seg * 8) * 2;
            long go = (long)(kt * 64 + row);
            CPA16(b + off,             kP + go * ldk + seg * 8);
            CPA16(b + 64*72*2 + off,   vP + go * ldv + seg * 8);
        }
        asm volatile("cp.async.commit_group;");
    };

    int nkt = causal ? (qt + 1) : (S_ / 64);
    loadKV(0, 0);

    asm volatile("cp.async.wait_group 0;");
    __syncthreads();
    int a_r = (lane & 7) + ((lane >> 3) & 1) * 8;
    int a_c8 = (lane >> 4) * 8;
    int bt_n = ((lane >> 4) << 3) + (lane & 7);
    int bt_k8 = ((lane >> 3) & 1) * 8;
    int bn_kr = ((lane >> 3) & 1) * 8 + (lane & 7);
    int bn_n8 = (lane >> 4) * 8;

    unsigned qa[4][4];
#pragma unroll
    for (int ks = 0; ks < 4; ks++) {
        unsigned off = (unsigned)(((wid * 16 + a_r) * 72) + ks * 16 + a_c8) * 2;
        LDSM4(qa[ks], sbase + QOFF + off);
    }

    float m0 = -1e30f, m1 = -1e30f, l0 = 0.f, l1 = 0.f;
    float4 oacc[8];
#pragma unroll
    for (int j = 0; j < 8; j++) oacc[j] = make_float4(0.f, 0.f, 0.f, 0.f);

    for (int kt = 0; kt < nkt; kt++) {
        int st = kt & 1;
        if (kt + 1 < nkt) {
            loadKV(st ^ 1, kt + 1);
            asm volatile("cp.async.wait_group 1;");
        } else {
            asm volatile("cp.async.wait_group 0;");
        }
        __syncthreads();
        unsigned kb = sbase + ST0 + st * STSZ;
        unsigned vb = kb + 64 * 72 * 2;

        float4 sacc[8];
#pragma unroll
        for (int j = 0; j < 8; j++) sacc[j] = make_float4(0.f, 0.f, 0.f, 0.f);
#pragma unroll
        for (int ks = 0; ks < 4; ks++) {
            unsigned kh[4][4];
#pragma unroll
            for (int jp = 0; jp < 4; jp++) {
                unsigned off = (unsigned)(((jp * 16 + bt_n) * 72) + ks * 16 + bt_k8) * 2;
                LDSM4(kh[jp], kb + off);
            }
#pragma unroll
            for (int j = 0; j < 8; j++) {
                int jp = j >> 1, o = (j & 1) << 1;
                MMA4(sacc[j], qa[ks], kh[jp][o], kh[jp][o + 1]);
            }
        }
        int row0 = qt * 64 + wid * 16 + g, row1 = row0 + 8;
        float rx0 = -1e30f, rx1 = -1e30f;
#pragma unroll
        for (int j = 0; j < 8; j++) {
            float4 s = sacc[j];
            s.x *= 0.125f; s.y *= 0.125f; s.z *= 0.125f; s.w *= 0.125f;
            if (causal && kt == qt) {
                int c0 = kt * 64 + j * 8 + 2 * tig, c1 = c0 + 1;
                if (c0 > row0) s.x = -1e30f;
                if (c1 > row0) s.y = -1e30f;
                if (c0 > row1) s.z = -1e30f;
                if (c1 > row1) s.w = -1e30f;
            }
            rx0 = fmaxf(rx0, fmaxf(s.x, s.y));
            rx1 = fmaxf(rx1, fmaxf(s.z, s.w));
            sacc[j] = s;
        }
        rx0 = fmaxf(rx0, __shfl_xor_sync(0xffffffffu, rx0, 1));
        rx0 = fmaxf(rx0, __shfl_xor_sync(0xffffffffu, rx0, 2));
        rx1 = fmaxf(rx1, __shfl_xor_sync(0xffffffffu, rx1, 1));
        rx1 = fmaxf(rx1, __shfl_xor_sync(0xffffffffu, rx1, 2));
        float m0n = fmaxf(m0, rx0), m1n = fmaxf(m1, rx1);
        float sc0 = __expf(m0 - m0n), sc1 = __expf(m1 - m1n);
        m0 = m0n; m1 = m1n;
        float rs0 = 0.f, rs1 = 0.f;
#pragma unroll
        for (int j = 0; j < 8; j++) {
            float4 s = sacc[j];
            s.x = __expf(s.x - m0n); s.y = __expf(s.y - m0n);
            s.z = __expf(s.z - m1n); s.w = __expf(s.w - m1n);
            rs0 += s.x + s.y; rs1 += s.z + s.w;
            sacc[j] = s;
        }
        rs0 += __shfl_xor_sync(0xffffffffu, rs0, 1);
        rs0 += __shfl_xor_sync(0xffffffffu, rs0, 2);
        rs1 += __shfl_xor_sync(0xffffffffu, rs1, 1);
        rs1 += __shfl_xor_sync(0xffffffffu, rs1, 2);
        l0 = l0 * sc0 + rs0; l1 = l1 * sc1 + rs1;
#pragma unroll
        for (int j = 0; j < 8; j++) {
            oacc[j].x *= sc0; oacc[j].y *= sc0;
            oacc[j].z *= sc1; oacc[j].w *= sc1;
        }
        unsigned pa[4][4];
#pragma unroll
        for (int c = 0; c < 4; c++) {
            float4 b0 = sacc[2 * c], b1 = sacc[2 * c + 1];
            pa[c][0] = pkh(b0.x, b0.y);
            pa[c][1] = pkh(b0.z, b0.w);
            pa[c][2] = pkh(b1.x, b1.y);
            pa[c][3] = pkh(b1.z, b1.w);
        }
#pragma unroll
        for (int ks = 0; ks < 4; ks++) {
            unsigned vh[4][4];
#pragma unroll
            for (int jp = 0; jp < 4; jp++) {
                unsigned off = (unsigned)(((ks * 16 + bn_kr) * 72) + jp * 16 + bn_n8) * 2;
                LDSM4T(vh[jp], vb + off);
            }
#pragma unroll
            for (int j = 0; j < 8; j++) {
                int jp = j >> 1, o = (j & 1) << 1;
                MMA4(oacc[j], pa[ks], vh[jp][o], vh[jp][o + 1]);
            }
        }
        __syncthreads();
    }

    float i0 = 1.f / l0, i1 = 1.f / l1;
    long r0 = (long)(zb * S_ + qt * 64 + wid * 16 + g) * D_ + zh * 64;
    long r1 = r0 + 8 * D_;
#pragma unroll
    for (int j = 0; j < 8; j++) {
        int col = j * 8 + 2 * tig;
        *(unsigned*)(Oh + r0 + col) = pkh(oacc[j].x * i0, oacc[j].y * i0);
        *(unsigned*)(Oh + r1 + col) = pkh(oacc[j].z * i1, oacc[j].w * i1);
    }
}

// =====================================================================
// linear GEMM — 2-stage, BK=64; occupancy 3 (this round's single change).
// =====================================================================
__global__ void __launch_bounds__(128, 3) gemm_tc(
    const h16* __restrict__ Ah, int lda,
    const h16* __restrict__ Bh, int ldb,
    const float* __restrict__ bias, const float* __restrict__ res,
    float* __restrict__ C, h16* __restrict__ Ch,
    int ldc, int K, int Nreal, int flags)
{
    constexpr int ASE = 128 * 72;
    constexpr int BSE = 128 * 72;
    constexpr int STE = ASE + BSE;
    extern __shared__ __align__(16) h16 sm[];

    int n0 = blockIdx.x * 128;
    int m0 = blockIdx.y * 128;

    int tid = threadIdx.x, lane = tid & 31, wid = tid >> 5;
    int wm = wid & 1, wn = wid >> 1;
    int g = lane >> 2, tig = lane & 3;
    unsigned sbase = (unsigned)__cvta_generic_to_shared(sm);
    int nch = K >> 6;

    auto load_stage = [&](int st, int k0) {
        unsigned aH = sbase + (unsigned)st * STE * 2;
        unsigned bH = aH + ASE * 2;
#pragma unroll
        for (int i = 0; i < 8; i++) {
            int c = tid + i * 128, row = c >> 3, kg = c & 7;
            unsigned off = (unsigned)(row * 72 + kg * 8) * 2;
            CPA16(aH + off, Ah + (long)(m0 + row) * lda + k0 + kg * 8);
        }
#pragma unroll
        for (int i = 0; i < 8; i++) {
            int c = tid + i * 128, row = c >> 3, kg = c & 7;
            unsigned off = (unsigned)(row * 72 + kg * 8) * 2;
            CPA16(bH + off, Bh + (long)(n0 + row) * ldb + k0 + kg * 8);
        }
        asm volatile("cp.async.commit_group;");
    };

    float4 acc[4][8];
#pragma unroll
    for (int i = 0; i < 4; i++)
#pragma unroll
        for (int j = 0; j < 8; j++) acc[i][j] = make_float4(0.f, 0.f, 0.f, 0.f);

    int a_r = (lane & 7) + ((lane >> 3) & 1) * 8;
    int a_c8 = (lane >> 4) * 8;
    int bt_n = ((lane >> 4) << 3) + (lane & 7);
    int bt_k8 = ((lane >> 3) & 1) * 8;

    load_stage(0, 0);
    for (int it = 0; it < nch; it++) {
        int st = it & 1;
        if (it + 1 < nch) {
            load_stage(st ^ 1, (it + 1) * 64);
            asm volatile("cp.async.wait_group 1;");
        } else {
            asm volatile("cp.async.wait_group 0;");
        }
        __syncthreads();
        unsigned aAh = sbase + (unsigned)st * STE * 2;
        unsigned aBh = aAh + ASE * 2;
#pragma unroll
        for (int ks = 0; ks < 4; ks++) {
            unsigned ah[4][4], bh[4][4];
#pragma unroll
            for (int mi = 0; mi < 4; mi++) {
                unsigned off = (unsigned)(((wm * 64 + mi * 16 + a_r) * 72) + ks * 16 + a_c8) * 2;
                LDSM4(ah[mi], aAh + off);
            }
#pragma unroll
            for (int jp = 0; jp < 4; jp++) {
                unsigned off = (unsigned)(((wn * 64 + jp * 16 + bt_n) * 72) + ks * 16 + bt_k8) * 2;
                LDSM4(bh[jp], aBh + off);
            }
#pragma unroll
            for (int mi = 0; mi < 4; mi++) {
#pragma unroll
                for (int j = 0; j < 8; j++) {
                    int jp = j >> 1, o = (j & 1) << 1;
                    MMA4(acc[mi][j], ah[mi], bh[jp][o], bh[jp][o + 1]);
                }
            }
        }
        __syncthreads();
    }

#pragma unroll
    for (int mi = 0; mi < 4; mi++) {
#pragma unroll
        for (int j = 0; j < 8; j++) {
            int col = n0 + wn * 64 + j * 8 + tig * 2;
            if (col >= Nreal) continue;
            int row0 = m0 + wm * 64 + mi * 16 + g, row1 = row0 + 8;
            float4 a = acc[mi][j];
            float2 bb = bias ? *(const float2*)(bias + col) : make_float2(0.f, 0.f);
            float2 v0, v1;
            v0.x = a.x + bb.x; v0.y = a.y + bb.y;
            v1.x = a.z + bb.x; v1.y = a.w + bb.y;
            if (res) {
                float2 q0 = *(const float2*)(res + (long)row0 * ldc + col);
                float2 q1 = *(const float2*)(res + (long)row1 * ldc + col);
                v0.x += q0.x; v0.y += q0.y; v1.x += q1.x; v1.y += q1.y;
            }
            if (flags & 2) {
                v0.x = fmaxf(v0.x, 0.f); v0.y = fmaxf(v0.y, 0.f);
                v1.x = fmaxf(v1.x, 0.f); v1.y = fmaxf(v1.y, 0.f);
            }
            if (C) {
                *(float2*)(C + (long)row0 * ldc + col) = v0;
                *(float2*)(C + (long)row1 * ldc + col) = v1;
            }
            if (Ch) {
                *(unsigned*)(Ch + (long)row0 * ldc + col) = pkh(v0.x, v0.y);
                *(unsigned*)(Ch + (long)row1 * ldc + col) = pkh(v1.x, v1.y);
            }
        }
    }
}

#define SMEMG (2 * (128*72 + 128*72) * 2)

static void gemmW(const h16* Ah, int K, const h16* Bh, int N, int Nreal,
                  const float* bias, const float* res,
                  float* C, h16* Ch, int ldc, int relu)
{
    gemm_tc<<<dim3(N / 128, TOK / 128, 1), 128, SMEMG>>>(
        Ah, K, Bh, K, bias, res, C, Ch, ldc, K, Nreal, relu ? 2 : 0);
}

extern "C" void kernel_launch(void* const* d_in, const int* in_sizes, int n_in,
                              void* d_out, int out_size)
{
    (void)in_sizes; (void)n_in; (void)out_size;
    const int* src = (const int*)d_in[0];
    const int* target = (const int*)d_in[2];
    const float* src_emb = (const float*)d_in[4];
    const float* tgt_emb = (const float*)d_in[5];
    const float* pos_emb = (const float*)d_in[6];
    const float* eaw = (const float*)d_in[7];
    const float* eab = (const float*)d_in[8];
    const float* elg = (const float*)d_in[9];
    const float* elb = (const float*)d_in[10];
    const float* ef1 = (const float*)d_in[11];
    const float* eb1 = (const float*)d_in[12];
    const float* ef2 = (const float*)d_in[13];
    const float* eb2 = (const float*)d_in[14];
    const float* eng = (const float*)d_in[15];
    const float* enb = (const float*)d_in[16];
    const float* daw = (const float*)d_in[17];
    const float* dab = (const float*)d_in[18];
    const float* dlg = (const float*)d_in[19];
    const float* dlb = (const float*)d_in[20];
    const float* df1 = (const float*)d_in[21];
    const float* db1 = (const float*)d_in[22];
    const float* df2 = (const float*)d_in[23];
    const float* db2 = (const float*)d_in[24];
    const float* dng = (const float*)d_in[25];
    const float* dnb = (const float*)d_in[26];
    const float* ow = (const float*)d_in[27];
    const float* ob = (const float*)d_in[28];
    float* out = (float*)d_out;

    cudaFuncSetAttribute(gemm_tc, cudaFuncAttributeMaxDynamicSharedMemorySize, SMEMG);
    cudaFuncSetAttribute(flash_kernel, cudaFuncAttributeMaxDynamicSharedMemorySize, SMEMF);

    float* x;
    h16 *xn, *qkv, *cq, *o, *mem, *ffh;
    h16 *wea, *wda, *we1, *we2, *wd1, *wd2, *wo;
    cudaGetSymbolAddress((void**)&x, g_x);
    cudaGetSymbolAddress((void**)&xn, g_xn);
    cudaGetSymbolAddress((void**)&qkv, g_qkv);
    cudaGetSymbolAddress((void**)&cq, g_cq);
    cudaGetSymbolAddress((void**)&o, g_o);
    cudaGetSymbolAddress((void**)&mem, g_mem);
    cudaGetSymbolAddress((void**)&ffh, g_ffh);
    cudaGetSymbolAddress((void**)&wea, g_wea);
    cudaGetSymbolAddress((void**)&wda, g_wda);
    cudaGetSymbolAddress((void**)&we1, g_we1);
    cudaGetSymbolAddress((void**)&we2, g_we2);
    cudaGetSymbolAddress((void**)&wd1, g_wd1);
    cudaGetSymbolAddress((void**)&wd2, g_wd2);
    cudaGetSymbolAddress((void**)&wo, g_wo);

    dim3 tb(32, 8);
    ttrans_kernel<<<dim3(24, 12, L_*4), tb>>>(eaw, wea, D_, D_, D_);
    ttrans_kernel<<<dim3(24, 12, L_*8), tb>>>(daw, wda, D_, D_, D_);
    ttrans_kernel<<<dim3(96, 12, L_), tb>>>(ef1, we1, D_, FF_, FF_);
    ttrans_kernel<<<dim3(24, 48, L_), tb>>>(ef2, we2, FF_, D_, D_);
    ttrans_kernel<<<dim3(96, 12, L_), tb>>>(df1, wd1, D_, FF_, FF_);
    ttrans_kernel<<<dim3(24, 48, L_), tb>>>(df2, wd2, FF_, D_, D_);
    ttrans_kernel<<<dim3(VP/32, 12, 1), tb>>>(ow, wo, D_, V_, VP);

    const long DD = (long)D_ * D_;
    const int nblk = (TOK * D_ + 255) / 256;
    dim3 fg(16, B_ * H_);

    // ================= encoder =================
    embed_kernel<<<nblk, 256>>>(src, src_emb, pos_emb, x);
    for (int l = 0; l < L_; l++) {
        const h16* wh = wea + (long)l * 4 * DD;
        const float* bb = eab + (long)l * 4 * D_;
        ln_kernel<<<TOK, 256>>>(x, elg + (l*2)*D_, elb + (l*2)*D_, xn);
        gemmW(xn, D_, wh, QKV, QKV, bb, nullptr, nullptr, qkv, QKV, 0);
        flash_kernel<<<fg, 128, SMEMF>>>(qkv, QKV, qkv + 768, QKV, qkv + 1536, QKV, o, 0);
        gemmW(o, D_, wh + 3*DD, D_, D_, bb + 3*D_, x, x, nullptr, D_, 0);
        ln_kernel<<<TOK, 256>>>(x, elg + (l*2+1)*D_, elb + (l*2+1)*D_, xn);
        gemmW(xn, D_, we1 + (long)l*FF_*D_, FF_, FF_, eb1 + l*FF_, nullptr, nullptr, ffh, FF_, 1);
        gemmW(ffh, FF_, we2 + (long)l*D_*FF_, D_, D_, eb2 + l*D_, x, x, nullptr, D_, 0);
    }
    ln_kernel<<<TOK, 256>>>(x, eng, enb, mem);

    // ================= decoder =================
    embed_kernel<<<nblk, 256>>>(target, tgt_emb, pos_emb, x);
    for (int l = 0; l < L_; l++) {
        const h16* wh = wda + (long)l * 8 * DD;
        const float* bb = dab + (long)l * 8 * D_;
        // causal self-attention
        ln_kernel<<<TOK, 256>>>(x, dlg + (l*3)*D_, dlb + (l*3)*D_, xn);
        gemmW(xn, D_, wh, QKV, QKV, bb, nullptr, nullptr, qkv, QKV, 0);
        flash_kernel<<<fg, 128, SMEMF>>>(qkv, QKV, qkv + 768, QKV, qkv + 1536, QKV, o, 1);
        gemmW(o, D_, wh + 3*DD, D_, D_, bb + 3*D_, x, x, nullptr, D_, 0);
        // cross-attention
        ln_kernel<<<TOK, 256>>>(x, dlg + (l*3+1)*D_, dlb + (l*3+1)*D_, xn);
        gemmW(xn, D_, wh + 4*DD, D_, D_, bb + 4*D_, nullptr, nullptr, cq, D_, 0);
        gemmW(mem, D_, wh + 5*DD, 2*D_, 2*D_, bb + 5*D_, nullptr, nullptr, qkv, 2*D_, 0);
        flash_kernel<<<fg, 128, SMEMF>>>(cq, D_, qkv, 2*D_, qkv + 768, 2*D_, o, 0);
        gemmW(o, D_, wh + 7*DD, D_, D_, bb + 7*D_, x, x, nullptr, D_, 0);
        // FFN
        ln_kernel<<<TOK, 256>>>(x, dlg + (l*3+2)*D_, dlb + (l*3+2)*D_, xn);
        gemmW(xn, D_, wd1 + (long)l*FF_*D_, FF_, FF_, db1 + l*FF_, nullptr, nullptr, ffh, FF_, 1);
        gemmW(ffh, FF_, wd2 + (long)l*D_*FF_, D_, D_, db2 + l*D_, x, x, nullptr, D_, 0);
    }
    ln_kernel<<<TOK, 256>>>(x, dng, dnb, xn);

    // ================= output projection =================
    gemmW(xn, D_, wo, VP, V_, ob, nullptr, out, nullptr, V_, 0);
}

// round 16
// speedup vs baseline: 1.5735x; 1.0005x over previous
#include <cuda_runtime.h>
#include <cuda_fp16.h>
#include <cstdint>

#define B_ 4
#define S_ 1024
#define D_ 768
#define H_ 12
#define L_ 4
#define V_ 8000
#define VP 8064
#define FF_ 3072
#define TOK 4096
#define QKV 2304
#define EPSF 1e-5f
typedef __half h16;
typedef __half2 h162;

// ---------------- scratch ----------------
__device__ float g_x[TOK * D_];
__device__ h16 g_xn[TOK * D_];
__device__ h16 g_qkv[TOK * QKV];
__device__ h16 g_cq[TOK * D_];
__device__ h16 g_o[TOK * D_];
__device__ h16 g_mem[TOK * D_];
__device__ h16 g_ffh[TOK * FF_];
__device__ h16 g_wea[L_*4*D_*D_];
__device__ h16 g_wda[L_*8*D_*D_];
__device__ h16 g_we1[L_*FF_*D_];
__device__ h16 g_we2[L_*D_*FF_];
__device__ h16 g_wd1[L_*FF_*D_];
__device__ h16 g_wd2[L_*D_*FF_];
__device__ h16 g_wo[(long)VP * D_];

// ---------------- transpose+convert weights ----------------
__global__ void ttrans_kernel(const float* __restrict__ W, h16* __restrict__ Wh,
                              int K, int N, int Npad)
{
    __shared__ float t[64][33];
    int z = blockIdx.z;
    W += (long)z * K * N; Wh += (long)z * Npad * K;
    int n0 = blockIdx.x * 32, k0 = blockIdx.y * 64;
    int tx = threadIdx.x, ty = threadIdx.y;
#pragma unroll
    for (int j = 0; j < 8; j++) {
        int k = k0 + ty + 8 * j, n = n0 + tx;
        t[ty + 8 * j][tx] = (n < N) ? W[(long)k * N + n] : 0.f;
    }
    __syncthreads();
#pragma unroll
    for (int j = 0; j < 4; j++) {
        int n = n0 + ty + 8 * j;
        h162 v;
        v.x = __float2half_rn(t[2 * tx][ty + 8 * j]);
        v.y = __float2half_rn(t[2 * tx + 1][ty + 8 * j]);
        *(h162*)(Wh + (long)n * K + k0 + 2 * tx) = v;
    }
}

// ---------------- embed ----------------
__global__ void embed_kernel(const int* __restrict__ tok, const float* __restrict__ emb,
                             const float* __restrict__ pos, float* __restrict__ out)
{
    int i = blockIdx.x * blockDim.x + threadIdx.x;
    if (i >= TOK * D_) return;
    int d = i % D_, t = i / D_, s = t % S_;
    out[i] = emb[(long)tok[t] * D_ + d] + pos[(long)s * D_ + d];
}

// ---------------- layernorm -> fp16 (warp-shuffle reduction) ----------------
__global__ void __launch_bounds__(256) ln_kernel(const float* __restrict__ x,
    const float* __restrict__ g, const float* __restrict__ b, h16* __restrict__ oh)
{
    int row = blockIdx.x, tid = threadIdx.x;
    int lane = tid & 31, wid = tid >> 5;
    const float* xr = x + (long)row * D_;
    float v[3], lsum = 0.f, lsq = 0.f;
#pragma unroll
    for (int i = 0; i < 3; i++) {
        float t = xr[tid + i * 256];
        v[i] = t; lsum += t; lsq += t * t;
    }
#pragma unroll
    for (int off = 16; off > 0; off >>= 1) {
        lsum += __shfl_xor_sync(0xffffffffu, lsum, off);
        lsq  += __shfl_xor_sync(0xffffffffu, lsq, off);
    }
    __shared__ float w1[8], w2[8];
    if (lane == 0) { w1[wid] = lsum; w2[wid] = lsq; }
    __syncthreads();
    float ts = 0.f, tq = 0.f;
#pragma unroll
    for (int i = 0; i < 8; i++) { ts += w1[i]; tq += w2[i]; }
    float mean = ts * (1.f / D_);
    float inv = rsqrtf(tq * (1.f / D_) - mean * mean + EPSF);
#pragma unroll
    for (int i = 0; i < 3; i++) {
        int d = tid + i * 256;
        oh[(long)row * D_ + d] = __float2half_rn((v[i] - mean) * inv * g[d] + b[d]);
    }
}

// ---------------- asm helpers ----------------
#define CPA16(dst, src) \
    asm volatile("cp.async.cg.shared.global [%0], [%1], 16;" :: "r"(dst), "l"(src))
#define LDSM4(r, addr) \
    asm volatile("ldmatrix.sync.aligned.m8n8.x4.shared.b16 {%0,%1,%2,%3}, [%4];" \
                 : "=r"((r)[0]), "=r"((r)[1]), "=r"((r)[2]), "=r"((r)[3]) : "r"(addr))
#define LDSM4T(r, addr) \
    asm volatile("ldmatrix.sync.aligned.m8n8.x4.trans.shared.b16 {%0,%1,%2,%3}, [%4];" \
                 : "=r"((r)[0]), "=r"((r)[1]), "=r"((r)[2]), "=r"((r)[3]) : "r"(addr))
#define MMA4(c, a, b0, b1)                                                    \
    asm volatile("mma.sync.aligned.m16n8k16.row.col.f32.f16.f16.f32 "         \
                 "{%0,%1,%2,%3}, {%4,%5,%6,%7}, {%8,%9}, {%0,%1,%2,%3};"      \
                 : "+f"((c).x), "+f"((c).y), "+f"((c).z), "+f"((c).w)         \
                 : "r"((a)[0]), "r"((a)[1]), "r"((a)[2]), "r"((a)[3]),        \
                   "r"(b0), "r"(b1))

__device__ __forceinline__ unsigned pkh(float x, float y)
{
    h162 hb;
    hb.x = __float2half_rn(x); hb.y = __float2half_rn(y);
    return *reinterpret_cast<unsigned*>(&hb);
}

// =====================================================================
// flash attention (1-term fp16): Q tile 64x64, KV streamed 64-row tiles.
// Occupancy 3 (this round's single change).
// =====================================================================
#define SMEMF ((64*72 + 2*2*64*72) * 2)

__global__ void __launch_bounds__(128, 3) flash_kernel(
    const h16* __restrict__ Qh, int ldq,
    const h16* __restrict__ Kh, int ldk,
    const h16* __restrict__ Vh, int ldv,
    h16* __restrict__ Oh, int causal)
{
    extern __shared__ __align__(16) h16 sm[];
    int qt = blockIdx.x, z = blockIdx.y, zb = z / H_, zh = z % H_;
    int tid = threadIdx.x, lane = tid & 31, wid = tid >> 5;
    int g = lane >> 2, tig = lane & 3;
    unsigned sbase = (unsigned)__cvta_generic_to_shared(sm);

    const h16* qP = Qh + (long)zb * S_ * ldq + zh * 64;
    const h16* kP = Kh + (long)zb * S_ * ldk + zh * 64;
    const h16* vP = Vh + (long)zb * S_ * ldv + zh * 64;

    const unsigned QOFF = 0;
    const unsigned ST0 = 64 * 72 * 2;
    const unsigned STSZ = 2 * 64 * 72 * 2;

#pragma unroll
    for (int i = 0; i < 4; i++) {
        int c = tid + i * 128, row = c >> 3, seg = c & 7;
        unsigned off = (unsigned)(row * 72 + seg * 8) * 2;
        CPA16(sbase + QOFF + off, qP + (long)(qt * 64 + row) * ldq + seg * 8);
    }
    asm volatile("cp.async.commit_group;");

    auto loadKV = [&](int st, int kt) {
        unsigned b = sbase + ST0 + st * STSZ;
#pragma unroll
        for (int i = 0; i < 4; i++) {
            int c = tid + i * 128, row = c >> 3, seg = c & 7;
            unsigned off = (unsigned)(row * 72 + seg * 8) * 2;
            long go = (long)(kt * 64 + row);
            CPA16(b + off,             kP + go * ldk + seg * 8);
            CPA16(b + 64*72*2 + off,   vP + go * ldv + seg * 8);
        }
        asm volatile("cp.async.commit_group;");
    };

    int nkt = causal ? (qt + 1) : (S_ / 64);
    loadKV(0, 0);

    asm volatile("cp.async.wait_group 0;");
    __syncthreads();
    int a_r = (lane & 7) + ((lane >> 3) & 1) * 8;
    int a_c8 = (lane >> 4) * 8;
    int bt_n = ((lane >> 4) << 3) + (lane & 7);
    int bt_k8 = ((lane >> 3) & 1) * 8;
    int bn_kr = ((lane >> 3) & 1) * 8 + (lane & 7);
    int bn_n8 = (lane >> 4) * 8;

    unsigned qa[4][4];
#pragma unroll
    for (int ks = 0; ks < 4; ks++) {
        unsigned off = (unsigned)(((wid * 16 + a_r) * 72) + ks * 16 + a_c8) * 2;
        LDSM4(qa[ks], sbase + QOFF + off);
    }

    float m0 = -1e30f, m1 = -1e30f, l0 = 0.f, l1 = 0.f;
    float4 oacc[8];
#pragma unroll
    for (int j = 0; j < 8; j++) oacc[j] = make_float4(0.f, 0.f, 0.f, 0.f);

    for (int kt = 0; kt < nkt; kt++) {
        int st = kt & 1;
        if (kt + 1 < nkt) {
            loadKV(st ^ 1, kt + 1);
            asm volatile("cp.async.wait_group 1;");
        } else {
            asm volatile("cp.async.wait_group 0;");
        }
        __syncthreads();
        unsigned kb = sbase + ST0 + st * STSZ;
        unsigned vb = kb + 64 * 72 * 2;

        float4 sacc[8];
#pragma unroll
        for (int j = 0; j < 8; j++) sacc[j] = make_float4(0.f, 0.f, 0.f, 0.f);
#pragma unroll
        for (int ks = 0; ks < 4; ks++) {
            unsigned kh[4][4];
#pragma unroll
            for (int jp = 0; jp < 4; jp++) {
                unsigned off = (unsigned)(((jp * 16 + bt_n) * 72) + ks * 16 + bt_k8) * 2;
                LDSM4(kh[jp], kb + off);
            }
#pragma unroll
            for (int j = 0; j < 8; j++) {
                int jp = j >> 1, o = (j & 1) << 1;
                MMA4(sacc[j], qa[ks], kh[jp][o], kh[jp][o + 1]);
            }
        }
        int row0 = qt * 64 + wid * 16 + g, row1 = row0 + 8;
        float rx0 = -1e30f, rx1 = -1e30f;
#pragma unroll
        for (int j = 0; j < 8; j++) {
            float4 s = sacc[j];
            s.x *= 0.125f; s.y *= 0.125f; s.z *= 0.125f; s.w *= 0.125f;
            if (causal && kt == qt) {
                int c0 = kt * 64 + j * 8 + 2 * tig, c1 = c0 + 1;
                if (c0 > row0) s.x = -1e30f;
                if (c1 > row0) s.y = -1e30f;
                if (c0 > row1) s.z = -1e30f;
                if (c1 > row1) s.w = -1e30f;
            }
            rx0 = fmaxf(rx0, fmaxf(s.x, s.y));
            rx1 = fmaxf(rx1, fmaxf(s.z, s.w));
            sacc[j] = s;
        }
        rx0 = fmaxf(rx0, __shfl_xor_sync(0xffffffffu, rx0, 1));
        rx0 = fmaxf(rx0, __shfl_xor_sync(0xffffffffu, rx0, 2));
        rx1 = fmaxf(rx1, __shfl_xor_sync(0xffffffffu, rx1, 1));
        rx1 = fmaxf(rx1, __shfl_xor_sync(0xffffffffu, rx1, 2));
        float m0n = fmaxf(m0, rx0), m1n = fmaxf(m1, rx1);
        float sc0 = __expf(m0 - m0n), sc1 = __expf(m1 - m1n);
        m0 = m0n; m1 = m1n;
        float rs0 = 0.f, rs1 = 0.f;
#pragma unroll
        for (int j = 0; j < 8; j++) {
            float4 s = sacc[j];
            s.x = __expf(s.x - m0n); s.y = __expf(s.y - m0n);
            s.z = __expf(s.z - m1n); s.w = __expf(s.w - m1n);
            rs0 += s.x + s.y; rs1 += s.z + s.w;
            sacc[j] = s;
        }
        rs0 += __shfl_xor_sync(0xffffffffu, rs0, 1);
        rs0 += __shfl_xor_sync(0xffffffffu, rs0, 2);
        rs1 += __shfl_xor_sync(0xffffffffu, rs1, 1);
        rs1 += __shfl_xor_sync(0xffffffffu, rs1, 2);
        l0 = l0 * sc0 + rs0; l1 = l1 * sc1 + rs1;
#pragma unroll
        for (int j = 0; j < 8; j++) {
            oacc[j].x *= sc0; oacc[j].y *= sc0;
            oacc[j].z *= sc1; oacc[j].w *= sc1;
        }
        unsigned pa[4][4];
#pragma unroll
        for (int c = 0; c < 4; c++) {
            float4 b0 = sacc[2 * c], b1 = sacc[2 * c + 1];
            pa[c][0] = pkh(b0.x, b0.y);
            pa[c][1] = pkh(b0.z, b0.w);
            pa[c][2] = pkh(b1.x, b1.y);
            pa[c][3] = pkh(b1.z, b1.w);
        }
#pragma unroll
        for (int ks = 0; ks < 4; ks++) {
            unsigned vh[4][4];
#pragma unroll
            for (int jp = 0; jp < 4; jp++) {
                unsigned off = (unsigned)(((ks * 16 + bn_kr) * 72) + jp * 16 + bn_n8) * 2;
                LDSM4T(vh[jp], vb + off);
            }
#pragma unroll
            for (int j = 0; j < 8; j++) {
                int jp = j >> 1, o = (j & 1) << 1;
                MMA4(oacc[j], pa[ks], vh[jp][o], vh[jp][o + 1]);
            }
        }
        __syncthreads();
    }

    float i0 = 1.f / l0, i1 = 1.f / l1;
    long r0 = (long)(zb * S_ + qt * 64 + wid * 16 + g) * D_ + zh * 64;
    long r1 = r0 + 8 * D_;
#pragma unroll
    for (int j = 0; j < 8; j++) {
        int col = j * 8 + 2 * tig;
        *(unsigned*)(Oh + r0 + col) = pkh(oacc[j].x * i0, oacc[j].y * i0);
        *(unsigned*)(Oh + r1 + col) = pkh(oacc[j].z * i1, oacc[j].w * i1);
    }
}

// =====================================================================
// linear GEMM — 2-stage, BK=64, occupancy 3 (R15-proven).
// =====================================================================
__global__ void __launch_bounds__(128, 3) gemm_tc(
    const h16* __restrict__ Ah, int lda,
    const h16* __restrict__ Bh, int ldb,
    const float* __restrict__ bias, const float* __restrict__ res,
    float* __restrict__ C, h16* __restrict__ Ch,
    int ldc, int K, int Nreal, int flags)
{
    constexpr int ASE = 128 * 72;
    constexpr int BSE = 128 * 72;
    constexpr int STE = ASE + BSE;
    extern __shared__ __align__(16) h16 sm[];

    int n0 = blockIdx.x * 128;
    int m0 = blockIdx.y * 128;

    int tid = threadIdx.x, lane = tid & 31, wid = tid >> 5;
    int wm = wid & 1, wn = wid >> 1;
    int g = lane >> 2, tig = lane & 3;
    unsigned sbase = (unsigned)__cvta_generic_to_shared(sm);
    int nch = K >> 6;

    auto load_stage = [&](int st, int k0) {
        unsigned aH = sbase + (unsigned)st * STE * 2;
        unsigned bH = aH + ASE * 2;
#pragma unroll
        for (int i = 0; i < 8; i++) {
            int c = tid + i * 128, row = c >> 3, kg = c & 7;
            unsigned off = (unsigned)(row * 72 + kg * 8) * 2;
            CPA16(aH + off, Ah + (long)(m0 + row) * lda + k0 + kg * 8);
        }
#pragma unroll
        for (int i = 0; i < 8; i++) {
            int c = tid + i * 128, row = c >> 3, kg = c & 7;
            unsigned off = (unsigned)(row * 72 + kg * 8) * 2;
            CPA16(bH + off, Bh + (long)(n0 + row) * ldb + k0 + kg * 8);
        }
        asm volatile("cp.async.commit_group;");
    };

    float4 acc[4][8];
#pragma unroll
    for (int i = 0; i < 4; i++)
#pragma unroll
        for (int j = 0; j < 8; j++) acc[i][j] = make_float4(0.f, 0.f, 0.f, 0.f);

    int a_r = (lane & 7) + ((lane >> 3) & 1) * 8;
    int a_c8 = (lane >> 4) * 8;
    int bt_n = ((lane >> 4) << 3) + (lane & 7);
    int bt_k8 = ((lane >> 3) & 1) * 8;

    load_stage(0, 0);
    for (int it = 0; it < nch; it++) {
        int st = it & 1;
        if (it + 1 < nch) {
            load_stage(st ^ 1, (it + 1) * 64);
            asm volatile("cp.async.wait_group 1;");
        } else {
            asm volatile("cp.async.wait_group 0;");
        }
        __syncthreads();
        unsigned aAh = sbase + (unsigned)st * STE * 2;
        unsigned aBh = aAh + ASE * 2;
#pragma unroll
        for (int ks = 0; ks < 4; ks++) {
            unsigned ah[4][4], bh[4][4];
#pragma unroll
            for (int mi = 0; mi < 4; mi++) {
                unsigned off = (unsigned)(((wm * 64 + mi * 16 + a_r) * 72) + ks * 16 + a_c8) * 2;
                LDSM4(ah[mi], aAh + off);
            }
#pragma unroll
            for (int jp = 0; jp < 4; jp++) {
                unsigned off = (unsigned)(((wn * 64 + jp * 16 + bt_n) * 72) + ks * 16 + bt_k8) * 2;
                LDSM4(bh[jp], aBh + off);
            }
#pragma unroll
            for (int mi = 0; mi < 4; mi++) {
#pragma unroll
                for (int j = 0; j < 8; j++) {
                    int jp = j >> 1, o = (j & 1) << 1;
                    MMA4(acc[mi][j], ah[mi], bh[jp][o], bh[jp][o + 1]);
                }
            }
        }
        __syncthreads();
    }

#pragma unroll
    for (int mi = 0; mi < 4; mi++) {
#pragma unroll
        for (int j = 0; j < 8; j++) {
            int col = n0 + wn * 64 + j * 8 + tig * 2;
            if (col >= Nreal) continue;
            int row0 = m0 + wm * 64 + mi * 16 + g, row1 = row0 + 8;
            float4 a = acc[mi][j];
            float2 bb = bias ? *(const float2*)(bias + col) : make_float2(0.f, 0.f);
            float2 v0, v1;
            v0.x = a.x + bb.x; v0.y = a.y + bb.y;
            v1.x = a.z + bb.x; v1.y = a.w + bb.y;
            if (res) {
                float2 q0 = *(const float2*)(res + (long)row0 * ldc + col);
                float2 q1 = *(const float2*)(res + (long)row1 * ldc + col);
                v0.x += q0.x; v0.y += q0.y; v1.x += q1.x; v1.y += q1.y;
            }
            if (flags & 2) {
                v0.x = fmaxf(v0.x, 0.f); v0.y = fmaxf(v0.y, 0.f);
                v1.x = fmaxf(v1.x, 0.f); v1.y = fmaxf(v1.y, 0.f);
            }
            if (C) {
                *(float2*)(C + (long)row0 * ldc + col) = v0;
                *(float2*)(C + (long)row1 * ldc + col) = v1;
            }
            if (Ch) {
                *(unsigned*)(Ch + (long)row0 * ldc + col) = pkh(v0.x, v0.y);
                *(unsigned*)(Ch + (long)row1 * ldc + col) = pkh(v1.x, v1.y);
            }
        }
    }
}

#define SMEMG (2 * (128*72 + 128*72) * 2)

static void gemmW(const h16* Ah, int K, const h16* Bh, int N, int Nreal,
                  const float* bias, const float* res,
                  float* C, h16* Ch, int ldc, int relu)
{
    gemm_tc<<<dim3(N / 128, TOK / 128, 1), 128, SMEMG>>>(
        Ah, K, Bh, K, bias, res, C, Ch, ldc, K, Nreal, relu ? 2 : 0);
}

extern "C" void kernel_launch(void* const* d_in, const int* in_sizes, int n_in,
                              void* d_out, int out_size)
{
    (void)in_sizes; (void)n_in; (void)out_size;
    const int* src = (const int*)d_in[0];
    const int* target = (const int*)d_in[2];
    const float* src_emb = (const float*)d_in[4];
    const float* tgt_emb = (const float*)d_in[5];
    const float* pos_emb = (const float*)d_in[6];
    const float* eaw = (const float*)d_in[7];
    const float* eab = (const float*)d_in[8];
    const float* elg = (const float*)d_in[9];
    const float* elb = (const float*)d_in[10];
    const float* ef1 = (const float*)d_in[11];
    const float* eb1 = (const float*)d_in[12];
    const float* ef2 = (const float*)d_in[13];
    const float* eb2 = (const float*)d_in[14];
    const float* eng = (const float*)d_in[15];
    const float* enb = (const float*)d_in[16];
    const float* daw = (const float*)d_in[17];
    const float* dab = (const float*)d_in[18];
    const float* dlg = (const float*)d_in[19];
    const float* dlb = (const float*)d_in[20];
    const float* df1 = (const float*)d_in[21];
    const float* db1 = (const float*)d_in[22];
    const float* df2 = (const float*)d_in[23];
    const float* db2 = (const float*)d_in[24];
    const float* dng = (const float*)d_in[25];
    const float* dnb = (const float*)d_in[26];
    const float* ow = (const float*)d_in[27];
    const float* ob = (const float*)d_in[28];
    float* out = (float*)d_out;

    cudaFuncSetAttribute(gemm_tc, cudaFuncAttributeMaxDynamicSharedMemorySize, SMEMG);
    cudaFuncSetAttribute(flash_kernel, cudaFuncAttributeMaxDynamicSharedMemorySize, SMEMF);

    float* x;
    h16 *xn, *qkv, *cq, *o, *mem, *ffh;
    h16 *wea, *wda, *we1, *we2, *wd1, *wd2, *wo;
    cudaGetSymbolAddress((void**)&x, g_x);
    cudaGetSymbolAddress((void**)&xn, g_xn);
    cudaGetSymbolAddress((void**)&qkv, g_qkv);
    cudaGetSymbolAddress((void**)&cq, g_cq);
    cudaGetSymbolAddress((void**)&o, g_o);
    cudaGetSymbolAddress((void**)&mem, g_mem);
    cudaGetSymbolAddress((void**)&ffh, g_ffh);
    cudaGetSymbolAddress((void**)&wea, g_wea);
    cudaGetSymbolAddress((void**)&wda, g_wda);
    cudaGetSymbolAddress((void**)&we1, g_we1);
    cudaGetSymbolAddress((void**)&we2, g_we2);
    cudaGetSymbolAddress((void**)&wd1, g_wd1);
    cudaGetSymbolAddress((void**)&wd2, g_wd2);
    cudaGetSymbolAddress((void**)&wo, g_wo);

    dim3 tb(32, 8);
    ttrans_kernel<<<dim3(24, 12, L_*4), tb>>>(eaw, wea, D_, D_, D_);
    ttrans_kernel<<<dim3(24, 12, L_*8), tb>>>(daw, wda, D_, D_, D_);
    ttrans_kernel<<<dim3(96, 12, L_), tb>>>(ef1, we1, D_, FF_, FF_);
    ttrans_kernel<<<dim3(24, 48, L_), tb>>>(ef2, we2, FF_, D_, D_);
    ttrans_kernel<<<dim3(96, 12, L_), tb>>>(df1, wd1, D_, FF_, FF_);
    ttrans_kernel<<<dim3(24, 48, L_), tb>>>(df2, wd2, FF_, D_, D_);
    ttrans_kernel<<<dim3(VP/32, 12, 1), tb>>>(ow, wo, D_, V_, VP);

    const long DD = (long)D_ * D_;
    const int nblk = (TOK * D_ + 255) / 256;
    dim3 fg(16, B_ * H_);

    // ================= encoder =================
    embed_kernel<<<nblk, 256>>>(src, src_emb, pos_emb, x);
    for (int l = 0; l < L_; l++) {
        const h16* wh = wea + (long)l * 4 * DD;
        const float* bb = eab + (long)l * 4 * D_;
        ln_kernel<<<TOK, 256>>>(x, elg + (l*2)*D_, elb + (l*2)*D_, xn);
        gemmW(xn, D_, wh, QKV, QKV, bb, nullptr, nullptr, qkv, QKV, 0);
        flash_kernel<<<fg, 128, SMEMF>>>(qkv, QKV, qkv + 768, QKV, qkv + 1536, QKV, o, 0);
        gemmW(o, D_, wh + 3*DD, D_, D_, bb + 3*D_, x, x, nullptr, D_, 0);
        ln_kernel<<<TOK, 256>>>(x, elg + (l*2+1)*D_, elb + (l*2+1)*D_, xn);
        gemmW(xn, D_, we1 + (long)l*FF_*D_, FF_, FF_, eb1 + l*FF_, nullptr, nullptr, ffh, FF_, 1);
        gemmW(ffh, FF_, we2 + (long)l*D_*FF_, D_, D_, eb2 + l*D_, x, x, nullptr, D_, 0);
    }
    ln_kernel<<<TOK, 256>>>(x, eng, enb, mem);

    // ================= decoder =================
    embed_kernel<<<nblk, 256>>>(target, tgt_emb, pos_emb, x);
    for (int l = 0; l < L_; l++) {
        const h16* wh = wda + (long)l * 8 * DD;
        const float* bb = dab + (long)l * 8 * D_;
        // causal self-attention
        ln_kernel<<<TOK, 256>>>(x, dlg + (l*3)*D_, dlb + (l*3)*D_, xn);
        gemmW(xn, D_, wh, QKV, QKV, bb, nullptr, nullptr, qkv, QKV, 0);
        flash_kernel<<<fg, 128, SMEMF>>>(qkv, QKV, qkv + 768, QKV, qkv + 1536, QKV, o, 1);
        gemmW(o, D_, wh + 3*DD, D_, D_, bb + 3*D_, x, x, nullptr, D_, 0);
        // cross-attention
        ln_kernel<<<TOK, 256>>>(x, dlg + (l*3+1)*D_, dlb + (l*3+1)*D_, xn);
        gemmW(xn, D_, wh + 4*DD, D_, D_, bb + 4*D_, nullptr, nullptr, cq, D_, 0);
        gemmW(mem, D_, wh + 5*DD, 2*D_, 2*D_, bb + 5*D_, nullptr, nullptr, qkv, 2*D_, 0);
        flash_kernel<<<fg, 128, SMEMF>>>(cq, D_, qkv, 2*D_, qkv + 768, 2*D_, o, 0);
        gemmW(o, D_, wh + 7*DD, D_, D_, bb + 7*D_, x, x, nullptr, D_, 0);
        // FFN
        ln_kernel<<<TOK, 256>>>(x, dlg + (l*3+2)*D_, dlb + (l*3+2)*D_, xn);
        gemmW(xn, D_, wd1 + (long)l*FF_*D_, FF_, FF_, db1 + l*FF_, nullptr, nullptr, ffh, FF_, 1);
        gemmW(ffh, FF_, wd2 + (long)l*D_*FF_, D_, D_, db2 + l*D_, x, x, nullptr, D_, 0);
    }
    ln_kernel<<<TOK, 256>>>(x, dng, dnb, xn);

    // ================= output projection =================
    gemmW(xn, D_, wo, VP, V_, ob, nullptr, out, nullptr, V_, 0);
}